// round 1
// baseline (speedup 1.0000x reference)
#include <cuda_runtime.h>
#include <cuda_bf16.h>
#include <cstdint>

// ---------------------------------------------------------------------------
// Problem constants (fixed by setup_inputs)
// ---------------------------------------------------------------------------
// B=8, H=W=64, N=4096, C=256, nh=8, nh2=4, hd=32, sr=8
#define BATCH 8
#define HH 64
#define WW 64
#define NTOK 4096
#define CH 256
#define HD 32
#define NH2 4

// Scratch buffers (device globals; allocation-free rule)
__device__ float g_q  [(size_t)BATCH * NTOK * CH];   // [B,N,C] q projection
__device__ float g_x1 [BATCH * 256 * CH];            // branch1 tokens [B,256,C]
__device__ float g_x2 [BATCH * 64 * CH];             // branch2 tokens [B,64,C]
__device__ float g_kv1[BATCH * 256 * CH];            // [B,256,256] (k|v)
__device__ float g_kv2[BATCH * 64 * CH];
__device__ float g_v1 [BATCH * 256 * 128];           // v + local conv, [B,256,128]
__device__ float g_v2 [BATCH * 64 * 128];
__device__ float g_cat[(size_t)BATCH * NTOK * CH];   // concat(o1,o2) [B,N,C]

// ---------------------------------------------------------------------------
// SGEMM: Out[m,d] = sum_c A[m,c] * W[d,c]  (+ bias[d]);  K = N = 256 fixed.
// 128x128 tile, BK=8, 8x8 per thread, 256 threads.
// ---------------------------------------------------------------------------
__global__ __launch_bounds__(256) void sgemm256(
    const float* __restrict__ A, const float* __restrict__ Wt,
    const float* __restrict__ bias, float* __restrict__ C)
{
    __shared__ float As[8][132];
    __shared__ float Bs[8][132];

    const int tid = threadIdx.x;
    const int m0 = blockIdx.x * 128;
    const int n0 = blockIdx.y * 128;
    const int ty = tid >> 4, tx = tid & 15;

    const int lr = tid >> 1;          // 0..127
    const int lc = (tid & 1) * 4;     // 0 or 4

    float acc[8][8];
#pragma unroll
    for (int i = 0; i < 8; i++)
#pragma unroll
        for (int j = 0; j < 8; j++) acc[i][j] = 0.f;

    for (int k0 = 0; k0 < 256; k0 += 8) {
        float4 a4 = *(const float4*)&A [(size_t)(m0 + lr) * 256 + k0 + lc];
        float4 b4 = *(const float4*)&Wt[(size_t)(n0 + lr) * 256 + k0 + lc];
        As[lc + 0][lr] = a4.x; As[lc + 1][lr] = a4.y;
        As[lc + 2][lr] = a4.z; As[lc + 3][lr] = a4.w;
        Bs[lc + 0][lr] = b4.x; Bs[lc + 1][lr] = b4.y;
        Bs[lc + 2][lr] = b4.z; Bs[lc + 3][lr] = b4.w;
        __syncthreads();
#pragma unroll
        for (int kk = 0; kk < 8; kk++) {
            float a[8], b[8];
#pragma unroll
            for (int i = 0; i < 8; i++) a[i] = As[kk][ty * 8 + i];
#pragma unroll
            for (int j = 0; j < 8; j++) b[j] = Bs[kk][tx * 8 + j];
#pragma unroll
            for (int i = 0; i < 8; i++)
#pragma unroll
                for (int j = 0; j < 8; j++) acc[i][j] += a[i] * b[j];
        }
        __syncthreads();
    }

    float bb[8];
#pragma unroll
    for (int j = 0; j < 8; j++) bb[j] = bias ? bias[n0 + tx * 8 + j] : 0.f;

#pragma unroll
    for (int i = 0; i < 8; i++) {
        const int m = m0 + ty * 8 + i;
        float* crow = &C[(size_t)m * 256 + n0 + tx * 8];
        float4 v0 = make_float4(acc[i][0] + bb[0], acc[i][1] + bb[1],
                                acc[i][2] + bb[2], acc[i][3] + bb[3]);
        float4 v1 = make_float4(acc[i][4] + bb[4], acc[i][5] + bb[5],
                                acc[i][6] + bb[6], acc[i][7] + bb[7]);
        *(float4*)(crow)     = v0;
        *(float4*)(crow + 4) = v1;
    }
}

// ---------------------------------------------------------------------------
// Depthwise conv (stride=kernel) + bias + LayerNorm(C) + exact GELU.
// One block per output token, 256 threads (one per channel).
// x layout: [B, N, C] (channel contiguous); x_[b,c,h,w] = x[b, h*W+w, c]
// ---------------------------------------------------------------------------
template<int K, int STRIDE, int OH>
__global__ __launch_bounds__(256) void dwconv_ln_gelu(
    const float* __restrict__ x, const float* __restrict__ w,
    const float* __restrict__ cb, const float* __restrict__ g,
    const float* __restrict__ bln, float* __restrict__ out)
{
    const int token = blockIdx.x;            // b*OH*OH + oh*OH + ow
    const int b  = token / (OH * OH);
    const int s  = token - b * (OH * OH);
    const int oh = s / OH, ow = s - oh * OH;
    const int c  = threadIdx.x;

    float acc = cb[c];
#pragma unroll
    for (int kh = 0; kh < K; kh++) {
#pragma unroll
        for (int kw = 0; kw < K; kw++) {
            const int ih = oh * STRIDE + kh;
            const int iw = ow * STRIDE + kw;
            acc += x[((size_t)b * NTOK + ih * WW + iw) * CH + c]
                 * w[c * K * K + kh * K + kw];
        }
    }

    // LN over channels: block reduce sum & sumsq
    __shared__ float red[16];
    float s1 = acc, s2 = acc * acc;
#pragma unroll
    for (int o = 16; o > 0; o >>= 1) {
        s1 += __shfl_xor_sync(0xffffffffu, s1, o);
        s2 += __shfl_xor_sync(0xffffffffu, s2, o);
    }
    if ((c & 31) == 0) { red[c >> 5] = s1; red[8 + (c >> 5)] = s2; }
    __syncthreads();
    if (c == 0) {
        float a = 0.f, bsum = 0.f;
#pragma unroll
        for (int i = 0; i < 8; i++) { a += red[i]; bsum += red[8 + i]; }
        red[0] = a; red[8] = bsum;
    }
    __syncthreads();
    const float mean = red[0] * (1.f / 256.f);
    const float var  = red[8] * (1.f / 256.f) - mean * mean;
    float y = (acc - mean) * rsqrtf(var + 1e-5f) * g[c] + bln[c];
    // exact GELU
    y = 0.5f * y * (1.0f + erff(y * 0.70710678118654752f));
    out[(size_t)token * CH + c] = y;
}

// ---------------------------------------------------------------------------
// v local conv: vnew[b,s,c'] = v[b,s,c'] + dwconv3x3(v_sp)[b,c',s] + bias
// v channel c' at token s lives at kv[(b*NS+s)*256 + 128 + c'].
// One block per token, 128 threads.
// ---------------------------------------------------------------------------
template<int HS>
__global__ __launch_bounds__(128) void vconv(
    const float* __restrict__ kv, const float* __restrict__ lcw,
    const float* __restrict__ lcb, float* __restrict__ vout)
{
    const int token = blockIdx.x;
    const int b  = token / (HS * HS);
    const int s  = token - b * (HS * HS);
    const int hs = s / HS, ws = s - hs * HS;
    const int c  = threadIdx.x;

    float acc = lcb[c];
#pragma unroll
    for (int kh = 0; kh < 3; kh++) {
#pragma unroll
        for (int kw = 0; kw < 3; kw++) {
            const int ih = hs - 1 + kh, iw = ws - 1 + kw;
            if (ih >= 0 && ih < HS && iw >= 0 && iw < HS)
                acc += kv[((size_t)b * HS * HS + ih * HS + iw) * 256 + 128 + c]
                     * lcw[c * 9 + kh * 3 + kw];
        }
    }
    vout[(size_t)token * 128 + c] =
        kv[(size_t)token * 256 + 128 + c] + acc;
}

// ---------------------------------------------------------------------------
// Attention: per (b, head) with NS keys. K/V staged in SMEM transposed
// ([32][NS+1] stride for conflict-free access). Warp-per-query, 8 warps,
// 128 queries per block (16 per warp).
//   k[b,h,s,e] = kv[(b*NS+s)*256 + h*32 + e]
//   v[b,h,s,e] = vbuf[(b*NS+s)*128 + h*32 + e]
//   out -> outc[(b*N+n)*256 + ooff + h*32 + e]
// ---------------------------------------------------------------------------
template<int NS>
__global__ __launch_bounds__(256) void attn_kernel(
    const float* __restrict__ qb, const float* __restrict__ kv,
    const float* __restrict__ vbuf, float* __restrict__ outc,
    int qoff, int ooff)
{
    extern __shared__ float sm[];
    float* ks    = sm;                      // [32][NS+1]
    float* vs    = sm + 32 * (NS + 1);      // [32][NS+1]
    float* probs = sm + 64 * (NS + 1);      // [8][NS]
    float* qs    = probs + 8 * NS;          // [8][33]

    const int bh = blockIdx.x;
    const int b  = bh >> 2;
    const int h  = bh & 3;
    const int tid = threadIdx.x;
    const int w = tid >> 5, lane = tid & 31;
    constexpr int KPL = NS / 32;
    const float scale = 0.17677669529663689f;  // 32^-0.5

    // stage K, V transposed
    for (int i = tid; i < NS * 32; i += 256) {
        const int s = i >> 5, e = i & 31;
        ks[e * (NS + 1) + s] = kv  [((size_t)b * NS + s) * 256 + h * 32 + e];
        vs[e * (NS + 1) + s] = vbuf[((size_t)b * NS + s) * 128 + h * 32 + e];
    }
    __syncthreads();

    for (int qi = 0; qi < 16; qi++) {
        const int n = blockIdx.y * 128 + w * 16 + qi;
        const float qv = qb[((size_t)b * NTOK + n) * 256 + qoff + h * 32 + lane];
        qs[w * 33 + lane] = qv;
        __syncwarp();

        float sc[KPL];
#pragma unroll
        for (int j = 0; j < KPL; j++) {
            const int s = j * 32 + lane;
            float a = 0.f;
#pragma unroll
            for (int e = 0; e < 32; e++)
                a += qs[w * 33 + e] * ks[e * (NS + 1) + s];
            sc[j] = a * scale;
        }

        // softmax over NS (distributed KPL per lane)
        float mx = sc[0];
#pragma unroll
        for (int j = 1; j < KPL; j++) mx = fmaxf(mx, sc[j]);
#pragma unroll
        for (int o = 16; o > 0; o >>= 1)
            mx = fmaxf(mx, __shfl_xor_sync(0xffffffffu, mx, o));
        float sum = 0.f;
#pragma unroll
        for (int j = 0; j < KPL; j++) { sc[j] = __expf(sc[j] - mx); sum += sc[j]; }
#pragma unroll
        for (int o = 16; o > 0; o >>= 1)
            sum += __shfl_xor_sync(0xffffffffu, sum, o);
#pragma unroll
        for (int j = 0; j < KPL; j++) probs[w * NS + j * 32 + lane] = sc[j];
        __syncwarp();

        // out[e=lane] = sum_s p[s] * v[s][e]
        float a = 0.f;
#pragma unroll 8
        for (int s = 0; s < NS; s++)
            a += probs[w * NS + s] * vs[lane * (NS + 1) + s];

        outc[((size_t)b * NTOK + n) * 256 + ooff + h * 32 + lane] = a / sum;
        __syncwarp();
    }
}

// ---------------------------------------------------------------------------
// launch
// ---------------------------------------------------------------------------
extern "C" void kernel_launch(void* const* d_in, const int* in_sizes, int n_in,
                              void* d_out, int out_size)
{
    const float* x      = (const float*)d_in[0];
    const float* q_w    = (const float*)d_in[1];
    const float* kv1_w  = (const float*)d_in[2];
    const float* kv2_w  = (const float*)d_in[3];
    const float* proj_w = (const float*)d_in[4];
    const float* proj_b = (const float*)d_in[5];
    const float* sr1_w  = (const float*)d_in[6];
    const float* sr1_b  = (const float*)d_in[7];
    const float* sr2_w  = (const float*)d_in[8];
    const float* sr2_b  = (const float*)d_in[9];
    const float* ln1_g  = (const float*)d_in[10];
    const float* ln1_b  = (const float*)d_in[11];
    const float* ln2_g  = (const float*)d_in[12];
    const float* ln2_b  = (const float*)d_in[13];
    const float* lc1_w  = (const float*)d_in[14];
    const float* lc1_b  = (const float*)d_in[15];
    const float* lc2_w  = (const float*)d_in[16];
    const float* lc2_b  = (const float*)d_in[17];
    float* out = (float*)d_out;

    float *p_q, *p_x1, *p_x2, *p_kv1, *p_kv2, *p_v1, *p_v2, *p_cat;
    cudaGetSymbolAddress((void**)&p_q,   g_q);
    cudaGetSymbolAddress((void**)&p_x1,  g_x1);
    cudaGetSymbolAddress((void**)&p_x2,  g_x2);
    cudaGetSymbolAddress((void**)&p_kv1, g_kv1);
    cudaGetSymbolAddress((void**)&p_kv2, g_kv2);
    cudaGetSymbolAddress((void**)&p_v1,  g_v1);
    cudaGetSymbolAddress((void**)&p_v2,  g_v2);
    cudaGetSymbolAddress((void**)&p_cat, g_cat);

    const int smem1 = (2 * 32 * 257 + 8 * 256 + 8 * 33) * 4;  // 75040 B
    const int smem2 = (2 * 32 * 65  + 8 * 64  + 8 * 33) * 4;  // 19744 B
    cudaFuncSetAttribute(attn_kernel<256>,
        cudaFuncAttributeMaxDynamicSharedMemorySize, smem1);
    cudaFuncSetAttribute(attn_kernel<64>,
        cudaFuncAttributeMaxDynamicSharedMemorySize, smem2);

    // 1. q = x @ q_w^T            [32768,256]
    sgemm256<<<dim3(32768 / 128, 2), 256>>>(x, q_w, nullptr, p_q);

    // 2/3. spatial reduction branches: dwconv + LN + GELU
    dwconv_ln_gelu<4, 4, 16><<<BATCH * 256, 256>>>(x, sr1_w, sr1_b, ln1_g, ln1_b, p_x1);
    dwconv_ln_gelu<8, 8, 8 ><<<BATCH * 64,  256>>>(x, sr2_w, sr2_b, ln2_g, ln2_b, p_x2);

    // 4/5. kv projections
    sgemm256<<<dim3(2048 / 128, 2), 256>>>(p_x1, kv1_w, nullptr, p_kv1);
    sgemm256<<<dim3(512  / 128, 2), 256>>>(p_x2, kv2_w, nullptr, p_kv2);

    // 6/7. v local conv (+residual)
    vconv<16><<<BATCH * 256, 128>>>(p_kv1, lc1_w, lc1_b, p_v1);
    vconv<8 ><<<BATCH * 64,  128>>>(p_kv2, lc2_w, lc2_b, p_v2);

    // 8/9. attention branches -> concat buffer
    attn_kernel<256><<<dim3(32, 32), 256, smem1>>>(p_q, p_kv1, p_v1, p_cat, 0,   0);
    attn_kernel<64 ><<<dim3(32, 32), 256, smem2>>>(p_q, p_kv2, p_v2, p_cat, 128, 128);

    // 10. output projection + bias
    sgemm256<<<dim3(32768 / 128, 2), 256>>>(p_cat, proj_w, proj_b, out);
}

// round 2
// speedup vs baseline: 1.0590x; 1.0590x over previous
#include <cuda_runtime.h>
#include <cuda_bf16.h>
#include <cstdint>

// ---------------------------------------------------------------------------
// Problem constants: B=8, H=W=64, N=4096, C=256, nh=8, nh2=4, hd=32, sr=8
// ---------------------------------------------------------------------------
#define BATCH 8
#define HH 64
#define WW 64
#define NTOK 4096
#define CH 256

// ---------------------------------------------------------------------------
// Scratch (device globals; allocation-free rule)
// ---------------------------------------------------------------------------
__device__ float g_q  [(size_t)BATCH * NTOK * CH];
__device__ float g_x1 [BATCH * 256 * CH];
__device__ float g_x2 [BATCH * 64 * CH];
__device__ float g_kv1[BATCH * 256 * CH];
__device__ float g_kv2[BATCH * 64 * CH];
__device__ float g_v1 [BATCH * 256 * 128];
__device__ float g_v2 [BATCH * 64 * 128];
__device__ float g_cat[(size_t)BATCH * NTOK * CH];

// bf16 split buffers (hi | lo | hi layout, K=768)
__device__ __nv_bfloat16 g_xe  [(size_t)BATCH * NTOK * 768];
__device__ __nv_bfloat16 g_cate[(size_t)BATCH * NTOK * 768];
__device__ __nv_bfloat16 g_x1e [BATCH * 256 * 768];
__device__ __nv_bfloat16 g_x2e [BATCH * 64 * 768];
__device__ __nv_bfloat16 g_qwe [256 * 768];
__device__ __nv_bfloat16 g_kv1we[256 * 768];
__device__ __nv_bfloat16 g_kv2we[256 * 768];
__device__ __nv_bfloat16 g_pwe [256 * 768];

// ---------------------------------------------------------------------------
// Split fp32 -> bf16 (hi|lo|hi) for activations
// ---------------------------------------------------------------------------
__global__ __launch_bounds__(256) void split_act(
    const float* __restrict__ in, __nv_bfloat16* __restrict__ out)
{
    const int i = blockIdx.x * 256 + threadIdx.x;
    const int m = i >> 8, c = i & 255;
    const float v = in[i];
    const __nv_bfloat16 hi = __float2bfloat16(v);
    const __nv_bfloat16 lo = __float2bfloat16(v - __bfloat162float(hi));
    __nv_bfloat16* row = out + (size_t)m * 768;
    row[c] = hi; row[256 + c] = lo; row[512 + c] = hi;
}

// Split fp32 -> bf16 (hi|hi|lo) for weights [256,256]
__global__ __launch_bounds__(256) void split_wgt(
    const float* __restrict__ in, __nv_bfloat16* __restrict__ out)
{
    const int i = blockIdx.x * 256 + threadIdx.x;
    const int n = i >> 8, c = i & 255;
    const float v = in[i];
    const __nv_bfloat16 hi = __float2bfloat16(v);
    const __nv_bfloat16 lo = __float2bfloat16(v - __bfloat162float(hi));
    __nv_bfloat16* row = out + (size_t)n * 768;
    row[c] = hi; row[256 + c] = hi; row[512 + c] = lo;
}

// ---------------------------------------------------------------------------
// Tensor-core GEMM: C[m,n] = sum_k A[m,k]*W[n,k], K=768, N=256.
// 128x256 block tile, 8 warps (2x4), 64x64 warp tile, mma.m16n8k16 bf16.
// Smem stride 40 bf16 (20 words) -> conflict-free fragment LDS.
// ---------------------------------------------------------------------------
__device__ __forceinline__ void mma16816(
    float* c, const uint32_t* a, const uint32_t* b)
{
    asm volatile(
        "mma.sync.aligned.m16n8k16.row.col.f32.bf16.bf16.f32 "
        "{%0,%1,%2,%3}, {%4,%5,%6,%7}, {%8,%9}, {%0,%1,%2,%3};"
        : "+f"(c[0]), "+f"(c[1]), "+f"(c[2]), "+f"(c[3])
        : "r"(a[0]), "r"(a[1]), "r"(a[2]), "r"(a[3]), "r"(b[0]), "r"(b[1]));
}

__global__ __launch_bounds__(256) void gemm_bf16_split(
    const __nv_bfloat16* __restrict__ A,   // [M,768]
    const __nv_bfloat16* __restrict__ Bw,  // [256,768]
    const float* __restrict__ bias,
    float* __restrict__ C)                 // [M,256]
{
    constexpr int LD = 40;
    __shared__ __align__(16) __nv_bfloat16 As[128 * LD];
    __shared__ __align__(16) __nv_bfloat16 Bs[256 * LD];

    const int tid = threadIdx.x;
    const int m0 = blockIdx.x * 128;
    const int w = tid >> 5, lane = tid & 31;
    const int wm = w & 1, wn = w >> 1;
    const int g = lane >> 2, qk = (lane & 3) * 2;

    float acc[4][8][4];
#pragma unroll
    for (int mt = 0; mt < 4; mt++)
#pragma unroll
        for (int nt = 0; nt < 8; nt++)
#pragma unroll
            for (int r = 0; r < 4; r++) acc[mt][nt][r] = 0.f;

    for (int k0 = 0; k0 < 768; k0 += 32) {
        // load A tile [128][32] : 512 16B-chunks
#pragma unroll
        for (int i = 0; i < 2; i++) {
            const int c = tid * 2 + i;
            const int row = c >> 2, ch = c & 3;
            *(uint4*)&As[row * LD + ch * 8] =
                *(const uint4*)&A[(size_t)(m0 + row) * 768 + k0 + ch * 8];
        }
        // load B tile [256][32] : 1024 chunks
#pragma unroll
        for (int i = 0; i < 4; i++) {
            const int c = i * 256 + tid;
            const int row = c >> 2, ch = c & 3;
            *(uint4*)&Bs[row * LD + ch * 8] =
                *(const uint4*)&Bw[(size_t)row * 768 + k0 + ch * 8];
        }
        __syncthreads();

#pragma unroll
        for (int ks = 0; ks < 2; ks++) {
            const int kk = ks * 16;
            uint32_t af[4][4], bf[8][2];
#pragma unroll
            for (int mt = 0; mt < 4; mt++) {
                const __nv_bfloat16* pa = &As[(wm * 64 + mt * 16 + g) * LD + kk + qk];
                af[mt][0] = *(const uint32_t*)pa;
                af[mt][1] = *(const uint32_t*)(pa + 8 * LD);
                af[mt][2] = *(const uint32_t*)(pa + 8);
                af[mt][3] = *(const uint32_t*)(pa + 8 * LD + 8);
            }
#pragma unroll
            for (int nt = 0; nt < 8; nt++) {
                const __nv_bfloat16* pb = &Bs[(wn * 64 + nt * 8 + g) * LD + kk + qk];
                bf[nt][0] = *(const uint32_t*)pb;
                bf[nt][1] = *(const uint32_t*)(pb + 8);
            }
#pragma unroll
            for (int mt = 0; mt < 4; mt++)
#pragma unroll
                for (int nt = 0; nt < 8; nt++)
                    mma16816(acc[mt][nt], af[mt], bf[nt]);
        }
        __syncthreads();
    }

    // epilogue
#pragma unroll
    for (int mt = 0; mt < 4; mt++) {
        const int r = m0 + wm * 64 + mt * 16 + g;
#pragma unroll
        for (int nt = 0; nt < 8; nt++) {
            const int col = wn * 64 + nt * 8 + qk;
            float b0 = bias ? bias[col] : 0.f;
            float b1 = bias ? bias[col + 1] : 0.f;
            *(float2*)&C[(size_t)r * 256 + col] =
                make_float2(acc[mt][nt][0] + b0, acc[mt][nt][1] + b1);
            *(float2*)&C[(size_t)(r + 8) * 256 + col] =
                make_float2(acc[mt][nt][2] + b0, acc[mt][nt][3] + b1);
        }
    }
}

// ---------------------------------------------------------------------------
// Depthwise conv (stride=kernel) + bias + LN(C) + exact GELU (unchanged)
// ---------------------------------------------------------------------------
template<int K, int STRIDE, int OH>
__global__ __launch_bounds__(256) void dwconv_ln_gelu(
    const float* __restrict__ x, const float* __restrict__ w,
    const float* __restrict__ cb, const float* __restrict__ g,
    const float* __restrict__ bln, float* __restrict__ out)
{
    const int token = blockIdx.x;
    const int b  = token / (OH * OH);
    const int s  = token - b * (OH * OH);
    const int oh = s / OH, ow = s - oh * OH;
    const int c  = threadIdx.x;

    float acc = cb[c];
#pragma unroll
    for (int kh = 0; kh < K; kh++)
#pragma unroll
        for (int kw = 0; kw < K; kw++) {
            const int ih = oh * STRIDE + kh;
            const int iw = ow * STRIDE + kw;
            acc += x[((size_t)b * NTOK + ih * WW + iw) * CH + c]
                 * w[c * K * K + kh * K + kw];
        }

    __shared__ float red[16];
    float s1 = acc, s2 = acc * acc;
#pragma unroll
    for (int o = 16; o > 0; o >>= 1) {
        s1 += __shfl_xor_sync(0xffffffffu, s1, o);
        s2 += __shfl_xor_sync(0xffffffffu, s2, o);
    }
    if ((c & 31) == 0) { red[c >> 5] = s1; red[8 + (c >> 5)] = s2; }
    __syncthreads();
    if (c == 0) {
        float a = 0.f, bsum = 0.f;
#pragma unroll
        for (int i = 0; i < 8; i++) { a += red[i]; bsum += red[8 + i]; }
        red[0] = a; red[8] = bsum;
    }
    __syncthreads();
    const float mean = red[0] * (1.f / 256.f);
    const float var  = red[8] * (1.f / 256.f) - mean * mean;
    float y = (acc - mean) * rsqrtf(var + 1e-5f) * g[c] + bln[c];
    y = 0.5f * y * (1.0f + erff(y * 0.70710678118654752f));
    out[(size_t)token * CH + c] = y;
}

// ---------------------------------------------------------------------------
// v local conv (+residual) (unchanged)
// ---------------------------------------------------------------------------
template<int HS>
__global__ __launch_bounds__(128) void vconv(
    const float* __restrict__ kv, const float* __restrict__ lcw,
    const float* __restrict__ lcb, float* __restrict__ vout)
{
    const int token = blockIdx.x;
    const int b  = token / (HS * HS);
    const int s  = token - b * (HS * HS);
    const int hs = s / HS, ws = s - hs * HS;
    const int c  = threadIdx.x;

    float acc = lcb[c];
#pragma unroll
    for (int kh = 0; kh < 3; kh++)
#pragma unroll
        for (int kw = 0; kw < 3; kw++) {
            const int ih = hs - 1 + kh, iw = ws - 1 + kw;
            if (ih >= 0 && ih < HS && iw >= 0 && iw < HS)
                acc += kv[((size_t)b * HS * HS + ih * HS + iw) * 256 + 128 + c]
                     * lcw[c * 9 + kh * 3 + kw];
        }
    vout[(size_t)token * 128 + c] = kv[(size_t)token * 256 + 128 + c] + acc;
}

// ---------------------------------------------------------------------------
// Fused attention, register-tiled. 32 queries/block, 256 threads.
// Phase 1: scores (4x(NS/32) tiles/thread, Q/K staged transposed in smem)
// Phase 2: softmax (row/warp), Phase 3: PV with float4 V.
// ---------------------------------------------------------------------------
template<int NS>
__global__ __launch_bounds__(256) void attn_tiled(
    const float* __restrict__ qb, const float* __restrict__ kv,
    const float* __restrict__ vbuf, float* __restrict__ outc,
    int qoff, int ooff)
{
    constexpr int SN  = NS / 32;     // score cols per thread
    constexpr int SST = NS + 4;      // Ss row stride
    extern __shared__ float sm[];
    float* Qs = sm;                  // [32 e][33 q]
    float* Ks = sm + 32 * 33;        // [32 e][NS s]
    float* Ss = Ks + 32 * NS;        // [32 q][SST]
    float* rs = Ss + 32 * SST;       // [32] row sums
    float* Vs = Ks;                  // alias: [NS s][32 e] after scores

    const int b = blockIdx.x >> 2, h = blockIdx.x & 3;
    const int q0 = blockIdx.y * 32;
    const int tid = threadIdx.x;
    const int lane = tid & 31, wrp = tid >> 5;

    // stage Q (transposed) and K (transposed), coalesced
    {
        const int e = lane;
#pragma unroll
        for (int i = 0; i < 4; i++) {
            const int qq = i * 8 + wrp;
            Qs[e * 33 + qq] = qb[((size_t)b * NTOK + q0 + qq) * CH + qoff + h * 32 + e];
        }
#pragma unroll 4
        for (int i = 0; i < NS / 8; i++) {
            const int s = i * 8 + wrp;
            Ks[e * NS + s] = kv[((size_t)b * NS + s) * CH + h * 32 + e];
        }
    }
    __syncthreads();

    // scores: rows wrp*4..+3, cols lane*SN..+SN-1
    const int qr = wrp * 4;
    const int sc0 = lane * SN;
    float acc[4][SN];
#pragma unroll
    for (int i = 0; i < 4; i++)
#pragma unroll
        for (int j = 0; j < SN; j++) acc[i][j] = 0.f;

#pragma unroll 8
    for (int kk = 0; kk < 32; kk++) {
        float a[4];
#pragma unroll
        for (int i = 0; i < 4; i++) a[i] = Qs[kk * 33 + qr + i];
        float bb[SN];
        if constexpr (SN == 8) {
            *(float4*)&bb[0] = *(const float4*)&Ks[kk * NS + sc0];
            *(float4*)&bb[4] = *(const float4*)&Ks[kk * NS + sc0 + 4];
        } else {
#pragma unroll
            for (int j = 0; j < SN; j++) bb[j] = Ks[kk * NS + sc0 + j];
        }
#pragma unroll
        for (int i = 0; i < 4; i++)
#pragma unroll
            for (int j = 0; j < SN; j++) acc[i][j] += a[i] * bb[j];
    }

    const float scale = 0.17677669529663689f;  // 32^-0.5
#pragma unroll
    for (int i = 0; i < 4; i++) {
        if constexpr (SN == 8) {
            float4 v0 = make_float4(acc[i][0] * scale, acc[i][1] * scale,
                                    acc[i][2] * scale, acc[i][3] * scale);
            float4 v1 = make_float4(acc[i][4] * scale, acc[i][5] * scale,
                                    acc[i][6] * scale, acc[i][7] * scale);
            *(float4*)&Ss[(qr + i) * SST + sc0] = v0;
            *(float4*)&Ss[(qr + i) * SST + sc0 + 4] = v1;
        } else {
#pragma unroll
            for (int j = 0; j < SN; j++)
                Ss[(qr + i) * SST + sc0 + j] = acc[i][j] * scale;
        }
    }
    __syncthreads();

    // stage V (overwrites Ks region — safe after sync)
    {
        const int e = lane;
#pragma unroll 4
        for (int i = 0; i < NS / 8; i++) {
            const int s = i * 8 + wrp;
            Vs[s * 32 + e] = vbuf[((size_t)b * NS + s) * 128 + h * 32 + e];
        }
    }

    // softmax: warp wrp owns rows qr..qr+3 of Ss
#pragma unroll
    for (int i = 0; i < 4; i++) {
        const int r = qr + i;
        float mx = -1e30f;
#pragma unroll
        for (int j = 0; j < SN; j++)
            mx = fmaxf(mx, Ss[r * SST + lane + j * 32]);
#pragma unroll
        for (int o = 16; o > 0; o >>= 1)
            mx = fmaxf(mx, __shfl_xor_sync(0xffffffffu, mx, o));
        float sum = 0.f;
#pragma unroll
        for (int j = 0; j < SN; j++) {
            const float p = __expf(Ss[r * SST + lane + j * 32] - mx);
            Ss[r * SST + lane + j * 32] = p;
            sum += p;
        }
#pragma unroll
        for (int o = 16; o > 0; o >>= 1)
            sum += __shfl_xor_sync(0xffffffffu, sum, o);
        if (lane == 0) rs[r] = sum;
    }
    __syncthreads();

    // PV: thread -> (q = tid/8, 4 consecutive e)
    {
        const int q = tid >> 3;
        const int e4 = (tid & 7) * 4;
        float4 o = make_float4(0.f, 0.f, 0.f, 0.f);
#pragma unroll 8
        for (int s = 0; s < NS; s++) {
            const float p = Ss[q * SST + s];
            const float4 v = *(const float4*)&Vs[s * 32 + e4];
            o.x += p * v.x; o.y += p * v.y; o.z += p * v.z; o.w += p * v.w;
        }
        const float inv = 1.0f / rs[q];
        float4 res = make_float4(o.x * inv, o.y * inv, o.z * inv, o.w * inv);
        *(float4*)&outc[((size_t)b * NTOK + q0 + q) * CH + ooff + h * 32 + e4] = res;
    }
}

// ---------------------------------------------------------------------------
// launch
// ---------------------------------------------------------------------------
extern "C" void kernel_launch(void* const* d_in, const int* in_sizes, int n_in,
                              void* d_out, int out_size)
{
    const float* x      = (const float*)d_in[0];
    const float* q_w    = (const float*)d_in[1];
    const float* kv1_w  = (const float*)d_in[2];
    const float* kv2_w  = (const float*)d_in[3];
    const float* proj_w = (const float*)d_in[4];
    const float* proj_b = (const float*)d_in[5];
    const float* sr1_w  = (const float*)d_in[6];
    const float* sr1_b  = (const float*)d_in[7];
    const float* sr2_w  = (const float*)d_in[8];
    const float* sr2_b  = (const float*)d_in[9];
    const float* ln1_g  = (const float*)d_in[10];
    const float* ln1_b  = (const float*)d_in[11];
    const float* ln2_g  = (const float*)d_in[12];
    const float* ln2_b  = (const float*)d_in[13];
    const float* lc1_w  = (const float*)d_in[14];
    const float* lc1_b  = (const float*)d_in[15];
    const float* lc2_w  = (const float*)d_in[16];
    const float* lc2_b  = (const float*)d_in[17];
    float* out = (float*)d_out;

    float *p_q, *p_x1, *p_x2, *p_kv1, *p_kv2, *p_v1, *p_v2, *p_cat;
    __nv_bfloat16 *p_xe, *p_cate, *p_x1e, *p_x2e, *p_qwe, *p_kv1we, *p_kv2we, *p_pwe;
    cudaGetSymbolAddress((void**)&p_q,    g_q);
    cudaGetSymbolAddress((void**)&p_x1,   g_x1);
    cudaGetSymbolAddress((void**)&p_x2,   g_x2);
    cudaGetSymbolAddress((void**)&p_kv1,  g_kv1);
    cudaGetSymbolAddress((void**)&p_kv2,  g_kv2);
    cudaGetSymbolAddress((void**)&p_v1,   g_v1);
    cudaGetSymbolAddress((void**)&p_v2,   g_v2);
    cudaGetSymbolAddress((void**)&p_cat,  g_cat);
    cudaGetSymbolAddress((void**)&p_xe,   g_xe);
    cudaGetSymbolAddress((void**)&p_cate, g_cate);
    cudaGetSymbolAddress((void**)&p_x1e,  g_x1e);
    cudaGetSymbolAddress((void**)&p_x2e,  g_x2e);
    cudaGetSymbolAddress((void**)&p_qwe,  g_qwe);
    cudaGetSymbolAddress((void**)&p_kv1we, g_kv1we);
    cudaGetSymbolAddress((void**)&p_kv2we, g_kv2we);
    cudaGetSymbolAddress((void**)&p_pwe,  g_pwe);

    const int smem1 = (32 * 33 + 32 * 256 + 32 * 260 + 32) * 4;  // 70400 B
    const int smem2 = (32 * 33 + 32 * 64 + 32 * 68 + 32) * 4;    // 21248 B
    cudaFuncSetAttribute(attn_tiled<256>,
        cudaFuncAttributeMaxDynamicSharedMemorySize, smem1);
    cudaFuncSetAttribute(attn_tiled<64>,
        cudaFuncAttributeMaxDynamicSharedMemorySize, smem2);

    // weight splits (tiny)
    split_wgt<<<256, 256>>>(q_w,    p_qwe);
    split_wgt<<<256, 256>>>(kv1_w,  p_kv1we);
    split_wgt<<<256, 256>>>(kv2_w,  p_kv2we);
    split_wgt<<<256, 256>>>(proj_w, p_pwe);

    // x -> bf16 split, q projection
    split_act<<<BATCH * NTOK, 256>>>(x, p_xe);
    gemm_bf16_split<<<256, 256>>>(p_xe, p_qwe, nullptr, p_q);

    // spatial-reduction branches
    dwconv_ln_gelu<4, 4, 16><<<BATCH * 256, 256>>>(x, sr1_w, sr1_b, ln1_g, ln1_b, p_x1);
    dwconv_ln_gelu<8, 8, 8 ><<<BATCH * 64,  256>>>(x, sr2_w, sr2_b, ln2_g, ln2_b, p_x2);

    split_act<<<BATCH * 256, 256>>>(p_x1, p_x1e);
    split_act<<<BATCH * 64,  256>>>(p_x2, p_x2e);
    gemm_bf16_split<<<16, 256>>>(p_x1e, p_kv1we, nullptr, p_kv1);
    gemm_bf16_split<<<4,  256>>>(p_x2e, p_kv2we, nullptr, p_kv2);

    vconv<16><<<BATCH * 256, 128>>>(p_kv1, lc1_w, lc1_b, p_v1);
    vconv<8 ><<<BATCH * 64,  128>>>(p_kv2, lc2_w, lc2_b, p_v2);

    // attention branches -> concat buffer
    attn_tiled<256><<<dim3(32, 128), 256, smem1>>>(p_q, p_kv1, p_v1, p_cat, 0,   0);
    attn_tiled<64 ><<<dim3(32, 128), 256, smem2>>>(p_q, p_kv2, p_v2, p_cat, 128, 128);

    // output projection
    split_act<<<BATCH * NTOK, 256>>>(p_cat, p_cate);
    gemm_bf16_split<<<256, 256>>>(p_cate, p_pwe, proj_b, out);
}

// round 4
// speedup vs baseline: 1.4658x; 1.3842x over previous
#include <cuda_runtime.h>
#include <cuda_bf16.h>
#include <cstdint>

// ---------------------------------------------------------------------------
// Problem constants: B=8, H=W=64, N=4096, C=256, nh=8, nh2=4, hd=32, sr=8
// ---------------------------------------------------------------------------
#define BATCH 8
#define HH 64
#define WW 64
#define NTOK 4096
#define CH 256

// ---------------------------------------------------------------------------
// Scratch (device globals)
// ---------------------------------------------------------------------------
__device__ __nv_bfloat16 g_xe  [(size_t)BATCH * NTOK * 768];  // x ext hi|lo|hi
__device__ __nv_bfloat16 g_cate[(size_t)BATCH * NTOK * 768];  // cat ext
__device__ __nv_bfloat16 g_x1e [BATCH * 256 * 768];
__device__ __nv_bfloat16 g_x2e [BATCH * 64 * 768];
__device__ __nv_bfloat16 g_qwe [256 * 768];
__device__ __nv_bfloat16 g_kv1we[256 * 768];
__device__ __nv_bfloat16 g_kv2we[256 * 768];
__device__ __nv_bfloat16 g_pwe [256 * 768];

__device__ uint32_t g_qp [(size_t)BATCH * NTOK * CH];  // q packed (hi,lo)
__device__ float    g_kv1[BATCH * 256 * CH];           // kv fp32 (for vconv)
__device__ float    g_kv2[BATCH * 64 * CH];
__device__ uint32_t g_k1p[BATCH * 256 * 128];          // k packed
__device__ uint32_t g_k2p[BATCH * 64 * 128];
__device__ uint32_t g_v1p[BATCH * 4 * 32 * 256];       // v^T packed [b,h][e][s]
__device__ uint32_t g_v2p[BATCH * 4 * 32 * 64];

// ---------------------------------------------------------------------------
// helpers
// ---------------------------------------------------------------------------
__device__ __forceinline__ uint32_t pack_hilo(float v) {
    __nv_bfloat16 h = __float2bfloat16(v);
    __nv_bfloat16 l = __float2bfloat16(v - __bfloat162float(h));
    return (uint32_t)__bfloat16_as_ushort(h) |
           ((uint32_t)__bfloat16_as_ushort(l) << 16);
}

__device__ __forceinline__ void mma16816(
    float* c, const uint32_t* a, const uint32_t* b)
{
    asm volatile(
        "mma.sync.aligned.m16n8k16.row.col.f32.bf16.bf16.f32 "
        "{%0,%1,%2,%3}, {%4,%5,%6,%7}, {%8,%9}, {%0,%1,%2,%3};"
        : "+f"(c[0]), "+f"(c[1]), "+f"(c[2]), "+f"(c[3])
        : "r"(a[0]), "r"(a[1]), "r"(a[2]), "r"(a[3]), "r"(b[0]), "r"(b[1]));
}

__device__ __forceinline__ void write_ext2(
    __nv_bfloat16* out, size_t row, int col, float v0, float v1)
{
    __nv_bfloat16 h0 = __float2bfloat16(v0), h1 = __float2bfloat16(v1);
    __nv_bfloat16 l0 = __float2bfloat16(v0 - __bfloat162float(h0));
    __nv_bfloat16 l1 = __float2bfloat16(v1 - __bfloat162float(h1));
    __nv_bfloat162 hp; hp.x = h0; hp.y = h1;
    __nv_bfloat162 lp; lp.x = l0; lp.y = l1;
    *(__nv_bfloat162*)&out[row * 768 + col]       = hp;
    *(__nv_bfloat162*)&out[row * 768 + 256 + col] = lp;
    *(__nv_bfloat162*)&out[row * 768 + 512 + col] = hp;
}

// ---------------------------------------------------------------------------
// weight splits: 4 matrices in one launch (hi|hi|lo layout for gemm B side)
// ---------------------------------------------------------------------------
__global__ __launch_bounds__(256) void split_wgt4(
    const float* __restrict__ w0, const float* __restrict__ w1,
    const float* __restrict__ w2, const float* __restrict__ w3,
    __nv_bfloat16* __restrict__ o0, __nv_bfloat16* __restrict__ o1,
    __nv_bfloat16* __restrict__ o2, __nv_bfloat16* __restrict__ o3)
{
    const int which = blockIdx.x >> 8;
    const int i = (blockIdx.x & 255) * 256 + threadIdx.x;
    const float* in = which == 0 ? w0 : which == 1 ? w1 : which == 2 ? w2 : w3;
    __nv_bfloat16* out = which == 0 ? o0 : which == 1 ? o1 : which == 2 ? o2 : o3;
    const int n = i >> 8, c = i & 255;
    const float v = in[i];
    const __nv_bfloat16 hi = __float2bfloat16(v);
    const __nv_bfloat16 lo = __float2bfloat16(v - __bfloat162float(hi));
    __nv_bfloat16* row = out + (size_t)n * 768;
    row[c] = hi; row[256 + c] = hi; row[512 + c] = lo;
}

// activation split (x only): hi|lo|hi
__global__ __launch_bounds__(256) void split_act(
    const float* __restrict__ in, __nv_bfloat16* __restrict__ out)
{
    const int i = blockIdx.x * 256 + threadIdx.x;
    const int m = i >> 8, c = i & 255;
    const float v = in[i];
    const __nv_bfloat16 hi = __float2bfloat16(v);
    const __nv_bfloat16 lo = __float2bfloat16(v - __bfloat162float(hi));
    __nv_bfloat16* row = out + (size_t)m * 768;
    row[c] = hi; row[256 + c] = lo; row[512 + c] = hi;
}

// ---------------------------------------------------------------------------
// Tensor-core GEMM (verified fragment mapping from round 2).
// C[m,n] = sum_k A[m,k]*W[n,k]; A ext [M,768], W ext [256,768].
// One block covers 128 x 256 output; 1-D grid over M tiles.
// MODE 0: fp32 out (+bias).  MODE 1: packed u32 out.  MODE 2: fp32 + packed k.
// ---------------------------------------------------------------------------
template<int MODE>
__global__ __launch_bounds__(256) void gemm_bf16_split(
    const __nv_bfloat16* __restrict__ A,
    const __nv_bfloat16* __restrict__ Bw,
    const float* __restrict__ bias,
    float* __restrict__ Cf,
    uint32_t* __restrict__ Cp)
{
    constexpr int LD = 40;
    __shared__ __align__(16) __nv_bfloat16 As[128 * LD];
    __shared__ __align__(16) __nv_bfloat16 Bs[256 * LD];

    const int tid = threadIdx.x;
    const int m0 = blockIdx.x * 128;
    const int w = tid >> 5, lane = tid & 31;
    const int wm = w & 1, wn = w >> 1;
    const int g = lane >> 2, qk = (lane & 3) * 2;

    float acc[4][8][4];
#pragma unroll
    for (int mt = 0; mt < 4; mt++)
#pragma unroll
        for (int nt = 0; nt < 8; nt++)
#pragma unroll
            for (int r = 0; r < 4; r++) acc[mt][nt][r] = 0.f;

    for (int k0 = 0; k0 < 768; k0 += 32) {
#pragma unroll
        for (int i = 0; i < 2; i++) {
            const int c = tid * 2 + i;
            const int row = c >> 2, ch = c & 3;
            *(uint4*)&As[row * LD + ch * 8] =
                *(const uint4*)&A[(size_t)(m0 + row) * 768 + k0 + ch * 8];
        }
#pragma unroll
        for (int i = 0; i < 4; i++) {
            const int c = i * 256 + tid;
            const int row = c >> 2, ch = c & 3;
            *(uint4*)&Bs[row * LD + ch * 8] =
                *(const uint4*)&Bw[(size_t)row * 768 + k0 + ch * 8];
        }
        __syncthreads();

#pragma unroll
        for (int ks = 0; ks < 2; ks++) {
            const int kk = ks * 16;
            uint32_t af[4][4], bf[8][2];
#pragma unroll
            for (int mt = 0; mt < 4; mt++) {
                const __nv_bfloat16* pa = &As[(wm * 64 + mt * 16 + g) * LD + kk + qk];
                af[mt][0] = *(const uint32_t*)pa;
                af[mt][1] = *(const uint32_t*)(pa + 8 * LD);
                af[mt][2] = *(const uint32_t*)(pa + 8);
                af[mt][3] = *(const uint32_t*)(pa + 8 * LD + 8);
            }
#pragma unroll
            for (int nt = 0; nt < 8; nt++) {
                const __nv_bfloat16* pb = &Bs[(wn * 64 + nt * 8 + g) * LD + kk + qk];
                bf[nt][0] = *(const uint32_t*)pb;
                bf[nt][1] = *(const uint32_t*)(pb + 8);
            }
#pragma unroll
            for (int mt = 0; mt < 4; mt++)
#pragma unroll
                for (int nt = 0; nt < 8; nt++)
                    mma16816(acc[mt][nt], af[mt], bf[nt]);
        }
        __syncthreads();
    }

#pragma unroll
    for (int mt = 0; mt < 4; mt++) {
        const int r = m0 + wm * 64 + mt * 16 + g;
#pragma unroll
        for (int nt = 0; nt < 8; nt++) {
            const int col = wn * 64 + nt * 8 + qk;
            if constexpr (MODE == 0) {
                const float b0 = bias ? bias[col] : 0.f;
                const float b1 = bias ? bias[col + 1] : 0.f;
                *(float2*)&Cf[(size_t)r * 256 + col] =
                    make_float2(acc[mt][nt][0] + b0, acc[mt][nt][1] + b1);
                *(float2*)&Cf[(size_t)(r + 8) * 256 + col] =
                    make_float2(acc[mt][nt][2] + b0, acc[mt][nt][3] + b1);
            } else if constexpr (MODE == 1) {
                uint2 p0 = make_uint2(pack_hilo(acc[mt][nt][0]), pack_hilo(acc[mt][nt][1]));
                uint2 p1 = make_uint2(pack_hilo(acc[mt][nt][2]), pack_hilo(acc[mt][nt][3]));
                *(uint2*)&Cp[(size_t)r * 256 + col] = p0;
                *(uint2*)&Cp[(size_t)(r + 8) * 256 + col] = p1;
            } else {
                *(float2*)&Cf[(size_t)r * 256 + col] =
                    make_float2(acc[mt][nt][0], acc[mt][nt][1]);
                *(float2*)&Cf[(size_t)(r + 8) * 256 + col] =
                    make_float2(acc[mt][nt][2], acc[mt][nt][3]);
                if (col < 128) {  // k half -> packed
                    uint2 p0 = make_uint2(pack_hilo(acc[mt][nt][0]), pack_hilo(acc[mt][nt][1]));
                    uint2 p1 = make_uint2(pack_hilo(acc[mt][nt][2]), pack_hilo(acc[mt][nt][3]));
                    *(uint2*)&Cp[(size_t)r * 128 + col] = p0;
                    *(uint2*)&Cp[(size_t)(r + 8) * 128 + col] = p1;
                }
            }
        }
    }
}

// ---------------------------------------------------------------------------
// Depthwise conv + bias + LN + exact GELU -> 768-ext bf16 output
// ---------------------------------------------------------------------------
template<int K, int STRIDE, int OH>
__global__ __launch_bounds__(256) void dwconv_ln_gelu(
    const float* __restrict__ x, const float* __restrict__ w,
    const float* __restrict__ cb, const float* __restrict__ g,
    const float* __restrict__ bln, __nv_bfloat16* __restrict__ out)
{
    const int token = blockIdx.x;
    const int b  = token / (OH * OH);
    const int s  = token - b * (OH * OH);
    const int oh = s / OH, ow = s - oh * OH;
    const int c  = threadIdx.x;

    float acc = cb[c];
#pragma unroll
    for (int kh = 0; kh < K; kh++)
#pragma unroll
        for (int kw = 0; kw < K; kw++) {
            const int ih = oh * STRIDE + kh;
            const int iw = ow * STRIDE + kw;
            acc += x[((size_t)b * NTOK + ih * WW + iw) * CH + c]
                 * w[c * K * K + kh * K + kw];
        }

    __shared__ float red[16];
    float s1 = acc, s2 = acc * acc;
#pragma unroll
    for (int o = 16; o > 0; o >>= 1) {
        s1 += __shfl_xor_sync(0xffffffffu, s1, o);
        s2 += __shfl_xor_sync(0xffffffffu, s2, o);
    }
    if ((c & 31) == 0) { red[c >> 5] = s1; red[8 + (c >> 5)] = s2; }
    __syncthreads();
    if (c == 0) {
        float a = 0.f, bsum = 0.f;
#pragma unroll
        for (int i = 0; i < 8; i++) { a += red[i]; bsum += red[8 + i]; }
        red[0] = a; red[8] = bsum;
    }
    __syncthreads();
    const float mean = red[0] * (1.f / 256.f);
    const float var  = red[8] * (1.f / 256.f) - mean * mean;
    float y = (acc - mean) * rsqrtf(var + 1e-5f) * g[c] + bln[c];
    y = 0.5f * y * (1.0f + erff(y * 0.70710678118654752f));

    const __nv_bfloat16 hi = __float2bfloat16(y);
    const __nv_bfloat16 lo = __float2bfloat16(y - __bfloat162float(hi));
    out[(size_t)token * 768 + c] = hi;
    out[(size_t)token * 768 + 256 + c] = lo;
    out[(size_t)token * 768 + 512 + c] = hi;
}

// ---------------------------------------------------------------------------
// v local conv (+residual) -> packed transposed V^T [b,h][e][s]
// ---------------------------------------------------------------------------
template<int HS>
__global__ __launch_bounds__(128) void vconv(
    const float* __restrict__ kv, const float* __restrict__ lcw,
    const float* __restrict__ lcb, uint32_t* __restrict__ vtp)
{
    constexpr int NS = HS * HS;
    const int token = blockIdx.x;
    const int b  = token / NS;
    const int s  = token - b * NS;
    const int hs = s / HS, ws = s - hs * HS;
    const int c  = threadIdx.x;

    float acc = lcb[c];
#pragma unroll
    for (int kh = 0; kh < 3; kh++)
#pragma unroll
        for (int kw = 0; kw < 3; kw++) {
            const int ih = hs - 1 + kh, iw = ws - 1 + kw;
            if (ih >= 0 && ih < HS && iw >= 0 && iw < HS)
                acc += kv[((size_t)b * NS + ih * HS + iw) * 256 + 128 + c]
                     * lcw[c * 9 + kh * 3 + kw];
        }
    const float v = kv[(size_t)token * 256 + 128 + c] + acc;
    const int h = c >> 5, e = c & 31;
    vtp[(((size_t)b * 4 + h) * 32 + e) * NS + s] = pack_hilo(v);
}

// ---------------------------------------------------------------------------
// Attention via mma. 64 queries/block, 256 threads, full NS.
// Packed (hi,lo) operands; 3-term split mma for QK^T and P.V.
// ---------------------------------------------------------------------------
template<int NS>
__global__ __launch_bounds__(256) void attn_mma(
    const uint32_t* __restrict__ qp,   // [B*4096][256]
    const uint32_t* __restrict__ kp,   // [B*NS][128]
    const uint32_t* __restrict__ vtp,  // [B*4][32][NS]
    __nv_bfloat16* __restrict__ cate,  // [B*4096][768]
    int qoff, int ooff)
{
    constexpr int NSP = NS + 2;        // Ss stride (fp32 / packed u32)
    constexpr int LDQ = 34;            // Qs/Ks stride (u32)
    constexpr int NT  = NS / 32;       // phase-1 s-tiles per warp
    constexpr int LOG = (NS == 256) ? 8 : 6;
    const float scale = 0.17677669529663689f;

    extern __shared__ float smf[];
    uint32_t* Qs = (uint32_t*)smf;                 // [64][LDQ]
    uint32_t* Ks = Qs + 64 * LDQ;                  // [NS][LDQ]
    float*    Ss = (float*)(Ks + NS * LDQ);        // [64][NSP]
    float*    rs = Ss + 64 * NSP;                  // [64]
    uint32_t* Vs = Ks;                             // alias [32][NSP]
    uint32_t* Sp = (uint32_t*)Ss;                  // packed alias

    const int b = blockIdx.x >> 2, h = blockIdx.x & 3;
    const int q0 = blockIdx.y * 64;
    const int tid = threadIdx.x, lane = tid & 31, w = tid >> 5;
    const int g = lane >> 2, qk = (lane & 3) * 2;

    // stage Q (64x32) and K (NSx32), conflict-free
    for (int i = tid; i < 64 * 32; i += 256) {
        const int r = i >> 5, e = i & 31;
        Qs[r * LDQ + e] = qp[((size_t)(b * 4096 + q0 + r)) * 256 + qoff + h * 32 + e];
    }
    for (int i = tid; i < NS * 32; i += 256) {
        const int s = i >> 5, e = i & 31;
        Ks[s * LDQ + e] = kp[((size_t)(b * NS + s)) * 128 + h * 32 + e];
    }
    __syncthreads();

    // ---- phase 1: S = Q K^T (K-dim 32 channels, 3-term split) ----
    {
        const int wm = w & 1, wn = w >> 1;
        float acc[2][NT][4];
#pragma unroll
        for (int mt = 0; mt < 2; mt++)
#pragma unroll
            for (int nt = 0; nt < NT; nt++)
#pragma unroll
                for (int r = 0; r < 4; r++) acc[mt][nt][r] = 0.f;

#pragma unroll
        for (int kc = 0; kc < 2; kc++) {
            const int kb = kc * 16;
            uint32_t ah[2][4], al[2][4];
#pragma unroll
            for (int mt = 0; mt < 2; mt++) {
                const int row = wm * 32 + mt * 16 + g;
                uint2 p0 = *(const uint2*)&Qs[row * LDQ + kb + qk];
                uint2 p1 = *(const uint2*)&Qs[(row + 8) * LDQ + kb + qk];
                uint2 p2 = *(const uint2*)&Qs[row * LDQ + kb + qk + 8];
                uint2 p3 = *(const uint2*)&Qs[(row + 8) * LDQ + kb + qk + 8];
                ah[mt][0] = __byte_perm(p0.x, p0.y, 0x5410);
                al[mt][0] = __byte_perm(p0.x, p0.y, 0x7632);
                ah[mt][1] = __byte_perm(p1.x, p1.y, 0x5410);
                al[mt][1] = __byte_perm(p1.x, p1.y, 0x7632);
                ah[mt][2] = __byte_perm(p2.x, p2.y, 0x5410);
                al[mt][2] = __byte_perm(p2.x, p2.y, 0x7632);
                ah[mt][3] = __byte_perm(p3.x, p3.y, 0x5410);
                al[mt][3] = __byte_perm(p3.x, p3.y, 0x7632);
            }
            uint32_t bh[NT][2], bl[NT][2];
#pragma unroll
            for (int nt = 0; nt < NT; nt++) {
                const int srow = wn * (NS / 4) + nt * 8 + g;
                uint2 p0 = *(const uint2*)&Ks[srow * LDQ + kb + qk];
                uint2 p1 = *(const uint2*)&Ks[srow * LDQ + kb + qk + 8];
                bh[nt][0] = __byte_perm(p0.x, p0.y, 0x5410);
                bl[nt][0] = __byte_perm(p0.x, p0.y, 0x7632);
                bh[nt][1] = __byte_perm(p1.x, p1.y, 0x5410);
                bl[nt][1] = __byte_perm(p1.x, p1.y, 0x7632);
            }
#pragma unroll
            for (int mt = 0; mt < 2; mt++)
#pragma unroll
                for (int nt = 0; nt < NT; nt++) {
                    mma16816(acc[mt][nt], ah[mt], bh[nt]);
                    mma16816(acc[mt][nt], al[mt], bh[nt]);
                    mma16816(acc[mt][nt], ah[mt], bl[nt]);
                }
        }
        // write scaled S (fp32)
#pragma unroll
        for (int mt = 0; mt < 2; mt++) {
            const int r = wm * 32 + mt * 16 + g;
#pragma unroll
            for (int nt = 0; nt < NT; nt++) {
                const int col = wn * (NS / 4) + nt * 8 + qk;
                *(float2*)&Ss[r * NSP + col] =
                    make_float2(acc[mt][nt][0] * scale, acc[mt][nt][1] * scale);
                *(float2*)&Ss[(r + 8) * NSP + col] =
                    make_float2(acc[mt][nt][2] * scale, acc[mt][nt][3] * scale);
            }
        }
    }
    __syncthreads();

    // stage V^T (overwrites Ks; safe after sync)
    for (int i = tid; i < 32 * NS; i += 256) {
        const int e = i >> LOG, s = i & (NS - 1);
        Vs[e * NSP + s] = vtp[(((size_t)(b * 4 + h)) * 32 + e) * NS + s];
    }

    // softmax: warp w -> rows w*8..w*8+7; pack p (hi,lo) in place
    {
        constexpr int JN = NS / 32;
#pragma unroll
        for (int i = 0; i < 8; i++) {
            const int r = w * 8 + i;
            float v[JN];
            float mx = -1e30f;
#pragma unroll
            for (int j = 0; j < JN; j++) {
                v[j] = Ss[r * NSP + lane + j * 32];
                mx = fmaxf(mx, v[j]);
            }
#pragma unroll
            for (int o = 16; o > 0; o >>= 1)
                mx = fmaxf(mx, __shfl_xor_sync(0xffffffffu, mx, o));
            float sum = 0.f;
#pragma unroll
            for (int j = 0; j < JN; j++) { v[j] = __expf(v[j] - mx); sum += v[j]; }
#pragma unroll
            for (int o = 16; o > 0; o >>= 1)
                sum += __shfl_xor_sync(0xffffffffu, sum, o);
#pragma unroll
            for (int j = 0; j < JN; j++)
                Sp[r * NSP + lane + j * 32] = pack_hilo(v[j]);
            if (lane == 0) rs[r] = sum;
        }
    }
    __syncthreads();

    // ---- phase 3: O = P V (K-dim NS, 3-term split), warps 4m x 2n ----
    {
        const int wm = w & 3, wn = w >> 2;
        float acc[2][4];
#pragma unroll
        for (int nt = 0; nt < 2; nt++)
#pragma unroll
            for (int r = 0; r < 4; r++) acc[nt][r] = 0.f;

#pragma unroll 4
        for (int kc = 0; kc < NS / 16; kc++) {
            const int kb = kc * 16;
            const int row = wm * 16 + g;
            uint32_t ah[4], al[4];
            {
                uint2 p0 = *(const uint2*)&Sp[row * NSP + kb + qk];
                uint2 p1 = *(const uint2*)&Sp[(row + 8) * NSP + kb + qk];
                uint2 p2 = *(const uint2*)&Sp[row * NSP + kb + qk + 8];
                uint2 p3 = *(const uint2*)&Sp[(row + 8) * NSP + kb + qk + 8];
                ah[0] = __byte_perm(p0.x, p0.y, 0x5410);
                al[0] = __byte_perm(p0.x, p0.y, 0x7632);
                ah[1] = __byte_perm(p1.x, p1.y, 0x5410);
                al[1] = __byte_perm(p1.x, p1.y, 0x7632);
                ah[2] = __byte_perm(p2.x, p2.y, 0x5410);
                al[2] = __byte_perm(p2.x, p2.y, 0x7632);
                ah[3] = __byte_perm(p3.x, p3.y, 0x5410);
                al[3] = __byte_perm(p3.x, p3.y, 0x7632);
            }
            uint32_t bh[2][2], bl[2][2];
#pragma unroll
            for (int nt = 0; nt < 2; nt++) {
                const int e = wn * 16 + nt * 8 + g;
                uint2 p0 = *(const uint2*)&Vs[e * NSP + kb + qk];
                uint2 p1 = *(const uint2*)&Vs[e * NSP + kb + qk + 8];
                bh[nt][0] = __byte_perm(p0.x, p0.y, 0x5410);
                bl[nt][0] = __byte_perm(p0.x, p0.y, 0x7632);
                bh[nt][1] = __byte_perm(p1.x, p1.y, 0x5410);
                bl[nt][1] = __byte_perm(p1.x, p1.y, 0x7632);
            }
#pragma unroll
            for (int nt = 0; nt < 2; nt++) {
                mma16816(acc[nt], ah, bh[nt]);
                mma16816(acc[nt], al, bh[nt]);
                mma16816(acc[nt], ah, bl[nt]);
            }
        }

        // epilogue: divide by rowsum, write 768-ext cat
        const int r0 = wm * 16 + g;
        const float inv0 = 1.0f / rs[r0];
        const float inv1 = 1.0f / rs[r0 + 8];
#pragma unroll
        for (int nt = 0; nt < 2; nt++) {
            const int col = ooff + h * 32 + wn * 16 + nt * 8 + qk;
            write_ext2(cate, (size_t)(b * 4096 + q0 + r0), col,
                       acc[nt][0] * inv0, acc[nt][1] * inv0);
            write_ext2(cate, (size_t)(b * 4096 + q0 + r0 + 8), col,
                       acc[nt][2] * inv1, acc[nt][3] * inv1);
        }
    }
}

// ---------------------------------------------------------------------------
// launch
// ---------------------------------------------------------------------------
extern "C" void kernel_launch(void* const* d_in, const int* in_sizes, int n_in,
                              void* d_out, int out_size)
{
    const float* x      = (const float*)d_in[0];
    const float* q_w    = (const float*)d_in[1];
    const float* kv1_w  = (const float*)d_in[2];
    const float* kv2_w  = (const float*)d_in[3];
    const float* proj_w = (const float*)d_in[4];
    const float* proj_b = (const float*)d_in[5];
    const float* sr1_w  = (const float*)d_in[6];
    const float* sr1_b  = (const float*)d_in[7];
    const float* sr2_w  = (const float*)d_in[8];
    const float* sr2_b  = (const float*)d_in[9];
    const float* ln1_g  = (const float*)d_in[10];
    const float* ln1_b  = (const float*)d_in[11];
    const float* ln2_g  = (const float*)d_in[12];
    const float* ln2_b  = (const float*)d_in[13];
    const float* lc1_w  = (const float*)d_in[14];
    const float* lc1_b  = (const float*)d_in[15];
    const float* lc2_w  = (const float*)d_in[16];
    const float* lc2_b  = (const float*)d_in[17];
    float* out = (float*)d_out;

    __nv_bfloat16 *p_xe, *p_cate, *p_x1e, *p_x2e, *p_qwe, *p_kv1we, *p_kv2we, *p_pwe;
    float *p_kv1, *p_kv2;
    uint32_t *p_qp, *p_k1p, *p_k2p, *p_v1p, *p_v2p;
    cudaGetSymbolAddress((void**)&p_xe,    g_xe);
    cudaGetSymbolAddress((void**)&p_cate,  g_cate);
    cudaGetSymbolAddress((void**)&p_x1e,   g_x1e);
    cudaGetSymbolAddress((void**)&p_x2e,   g_x2e);
    cudaGetSymbolAddress((void**)&p_qwe,   g_qwe);
    cudaGetSymbolAddress((void**)&p_kv1we, g_kv1we);
    cudaGetSymbolAddress((void**)&p_kv2we, g_kv2we);
    cudaGetSymbolAddress((void**)&p_pwe,   g_pwe);
    cudaGetSymbolAddress((void**)&p_kv1,   g_kv1);
    cudaGetSymbolAddress((void**)&p_kv2,   g_kv2);
    cudaGetSymbolAddress((void**)&p_qp,    g_qp);
    cudaGetSymbolAddress((void**)&p_k1p,   g_k1p);
    cudaGetSymbolAddress((void**)&p_k2p,   g_k2p);
    cudaGetSymbolAddress((void**)&p_v1p,   g_v1p);
    cudaGetSymbolAddress((void**)&p_v2p,   g_v2p);

    // attn smem: Qs+Ks (u32, LDQ=34) + Ss fp32 (NS+2) + rs
    const int smem1 = (64 * 34 + 256 * 34) * 4 + 64 * 258 * 4 + 64 * 4;  // 109,824
    const int smem2 = (64 * 34 + 64 * 34) * 4 + 64 * 66 * 4 + 64 * 4;    //  34,560
    cudaFuncSetAttribute(attn_mma<256>,
        cudaFuncAttributeMaxDynamicSharedMemorySize, smem1);
    cudaFuncSetAttribute(attn_mma<64>,
        cudaFuncAttributeMaxDynamicSharedMemorySize, smem2);

    // 1. weight splits (single launch)
    split_wgt4<<<1024, 256>>>(q_w, kv1_w, kv2_w, proj_w,
                              p_qwe, p_kv1we, p_kv2we, p_pwe);
    // 2. x -> ext
    split_act<<<BATCH * NTOK, 256>>>(x, p_xe);
    // 3. q projection -> packed      (1-D grid: 256 M-tiles, NO duplication)
    gemm_bf16_split<1><<<256, 256>>>(p_xe, p_qwe, nullptr, nullptr, p_qp);
    // 4/5. spatial reduction -> ext directly
    dwconv_ln_gelu<4, 4, 16><<<BATCH * 256, 256>>>(x, sr1_w, sr1_b, ln1_g, ln1_b, p_x1e);
    dwconv_ln_gelu<8, 8, 8 ><<<BATCH * 64,  256>>>(x, sr2_w, sr2_b, ln2_g, ln2_b, p_x2e);
    // 6/7. kv projections -> fp32 kv + packed k
    gemm_bf16_split<2><<<16, 256>>>(p_x1e, p_kv1we, nullptr, p_kv1, p_k1p);
    gemm_bf16_split<2><<<4,  256>>>(p_x2e, p_kv2we, nullptr, p_kv2, p_k2p);
    // 8/9. v local conv -> packed V^T
    vconv<16><<<BATCH * 256, 128>>>(p_kv1, lc1_w, lc1_b, p_v1p);
    vconv<8 ><<<BATCH * 64,  128>>>(p_kv2, lc2_w, lc2_b, p_v2p);
    // 10/11. attention -> ext cat
    attn_mma<256><<<dim3(32, 64), 256, smem1>>>(p_qp, p_k1p, p_v1p, p_cate, 0,   0);
    attn_mma<64 ><<<dim3(32, 64), 256, smem2>>>(p_qp, p_k2p, p_v2p, p_cate, 128, 128);
    // 12. output projection
    gemm_bf16_split<0><<<256, 256>>>(p_cate, p_pwe, proj_b, out, nullptr);
}

// round 5
// speedup vs baseline: 1.9844x; 1.3538x over previous
#include <cuda_runtime.h>
#include <cuda_bf16.h>
#include <cstdint>

// Problem constants: B=8, H=W=64, N=4096, C=256, nh=8, nh2=4, hd=32, sr=8
#define BATCH 8
#define NTOK 4096
#define CH 256

// ---------------------------------------------------------------------------
// Scratch (device globals)
// ---------------------------------------------------------------------------
__device__ uint32_t g_xp  [(size_t)BATCH * NTOK * CH];   // x packed (hi,lo)
__device__ uint32_t g_qp  [(size_t)BATCH * NTOK * CH];   // q packed
__device__ uint32_t g_catp[(size_t)BATCH * NTOK * CH];   // cat packed
__device__ uint32_t g_x1p [BATCH * 256 * CH];
__device__ uint32_t g_x2p [BATCH * 64 * CH];
__device__ float    g_kv1 [BATCH * 256 * CH];
__device__ float    g_kv2 [BATCH * 64 * CH];
__device__ uint32_t g_k1p [BATCH * 256 * 128];
__device__ uint32_t g_k2p [BATCH * 64 * 128];
__device__ uint32_t g_v1p [BATCH * 4 * 32 * 256];        // V^T packed [b,h][e][s]
__device__ uint32_t g_v2p [BATCH * 4 * 32 * 64];
// weight splits
__device__ __nv_bfloat16 g_qwh [256 * 256], g_qwl [256 * 256];
__device__ __nv_bfloat16 g_k1wh[256 * 256], g_k1wl[256 * 256];
__device__ __nv_bfloat16 g_k2wh[256 * 256], g_k2wl[256 * 256];
__device__ __nv_bfloat16 g_pwh [256 * 256], g_pwl [256 * 256];

// ---------------------------------------------------------------------------
// helpers
// ---------------------------------------------------------------------------
__device__ __forceinline__ uint32_t pack_hilo(float v) {
    __nv_bfloat16 h = __float2bfloat16(v);
    __nv_bfloat16 l = __float2bfloat16(v - __bfloat162float(h));
    return (uint32_t)__bfloat16_as_ushort(h) |
           ((uint32_t)__bfloat16_as_ushort(l) << 16);
}

__device__ __forceinline__ void mma16816(
    float* c, const uint32_t* a, const uint32_t* b)
{
    asm volatile(
        "mma.sync.aligned.m16n8k16.row.col.f32.bf16.bf16.f32 "
        "{%0,%1,%2,%3}, {%4,%5,%6,%7}, {%8,%9}, {%0,%1,%2,%3};"
        : "+f"(c[0]), "+f"(c[1]), "+f"(c[2]), "+f"(c[3])
        : "r"(a[0]), "r"(a[1]), "r"(a[2]), "r"(a[3]), "r"(b[0]), "r"(b[1]));
}

__device__ __forceinline__ void cpa16(void* dst, const void* src) {
    uint32_t d = (uint32_t)__cvta_generic_to_shared(dst);
    asm volatile("cp.async.cg.shared.global [%0], [%1], 16;\n"
                 :: "r"(d), "l"(src));
}

// ---------------------------------------------------------------------------
// split kernels
// ---------------------------------------------------------------------------
__global__ __launch_bounds__(256) void split_x(
    const float* __restrict__ in, uint32_t* __restrict__ out)
{
    const size_t i = ((size_t)blockIdx.x * 256 + threadIdx.x) * 4;
    float4 v = *(const float4*)&in[i];
    uint4 o = make_uint4(pack_hilo(v.x), pack_hilo(v.y),
                         pack_hilo(v.z), pack_hilo(v.w));
    *(uint4*)&out[i] = o;
}

__global__ __launch_bounds__(256) void split_wgt4(
    const float* __restrict__ w0, const float* __restrict__ w1,
    const float* __restrict__ w2, const float* __restrict__ w3,
    __nv_bfloat16* __restrict__ h0, __nv_bfloat16* __restrict__ l0,
    __nv_bfloat16* __restrict__ h1, __nv_bfloat16* __restrict__ l1,
    __nv_bfloat16* __restrict__ h2, __nv_bfloat16* __restrict__ l2,
    __nv_bfloat16* __restrict__ h3, __nv_bfloat16* __restrict__ l3)
{
    const int which = blockIdx.x >> 8;
    const int i = (blockIdx.x & 255) * 256 + threadIdx.x;
    const float* in = which == 0 ? w0 : which == 1 ? w1 : which == 2 ? w2 : w3;
    __nv_bfloat16* oh = which == 0 ? h0 : which == 1 ? h1 : which == 2 ? h2 : h3;
    __nv_bfloat16* ol = which == 0 ? l0 : which == 1 ? l1 : which == 2 ? l2 : l3;
    const float v = in[i];
    const __nv_bfloat16 hi = __float2bfloat16(v);
    oh[i] = hi;
    ol[i] = __float2bfloat16(v - __bfloat162float(hi));
}

// ---------------------------------------------------------------------------
// Pipelined tensor-core GEMM. C[m,n] = sum_k A[m,k]*W[n,k]; K=256, N=256.
// A packed u32 [M,256]; W split Whi/Wlo bf16 [256,256].
// 3-term split: ah*wh + al*wh + ah*wl. 512 threads, 3-stage cp.async.
// MODE 0: fp32 out (+bias). MODE 1: packed out. MODE 2: fp32 + packed k-half.
// ---------------------------------------------------------------------------
template<int MODE>
__global__ __launch_bounds__(512) void gemm_pk(
    const uint32_t* __restrict__ A,
    const __nv_bfloat16* __restrict__ Wh,
    const __nv_bfloat16* __restrict__ Wl,
    const float* __restrict__ bias,
    float* __restrict__ Cf, uint32_t* __restrict__ Cp)
{
    constexpr int LDA = 40;   // u32 words per A row
    constexpr int LDB = 40;   // bf16 per B row
    constexpr int ASZ = 128 * LDA;
    constexpr int BSZ = 256 * LDB;

    extern __shared__ __align__(16) char smraw[];
    uint32_t*      Ap = (uint32_t*)smraw;                 // [3][128][LDA]
    __nv_bfloat16* Bh = (__nv_bfloat16*)(Ap + 3 * ASZ);   // [3][256][LDB]
    __nv_bfloat16* Bl = Bh + 3 * BSZ;                     // [3][256][LDB]

    const int tid = threadIdx.x;
    const int m0 = blockIdx.x * 128;
    const int w = tid >> 5, lane = tid & 31;
    const int wm = w & 3, wn = w >> 2;          // 4 x 4 warps, 32x64 tile
    const int g = lane >> 2, qk = (lane & 3) * 2;

    auto load_stage = [&](int s, int k0) {
#pragma unroll
        for (int i = 0; i < 2; i++) {            // A: 1024 chunks
            const int c = tid + i * 512;
            const int row = c >> 3, ch = c & 7;
            cpa16(&Ap[s * ASZ + row * LDA + ch * 4],
                  &A[(size_t)(m0 + row) * 256 + k0 + ch * 4]);
        }
#pragma unroll
        for (int i = 0; i < 2; i++) {            // Bh: 1024 chunks
            const int c = tid + i * 512;
            const int row = c >> 2, ch = c & 3;
            cpa16(&Bh[s * BSZ + row * LDB + ch * 8],
                  &Wh[(size_t)row * 256 + k0 + ch * 8]);
        }
#pragma unroll
        for (int i = 0; i < 2; i++) {            // Bl
            const int c = tid + i * 512;
            const int row = c >> 2, ch = c & 3;
            cpa16(&Bl[s * BSZ + row * LDB + ch * 8],
                  &Wl[(size_t)row * 256 + k0 + ch * 8]);
        }
        asm volatile("cp.async.commit_group;\n" ::: "memory");
    };

    float acc[2][8][4];
#pragma unroll
    for (int mt = 0; mt < 2; mt++)
#pragma unroll
        for (int nt = 0; nt < 8; nt++)
#pragma unroll
            for (int r = 0; r < 4; r++) acc[mt][nt][r] = 0.f;

    load_stage(0, 0);
    load_stage(1, 32);

    for (int it = 0; it < 8; it++) {
        if (it < 7) asm volatile("cp.async.wait_group 1;\n" ::: "memory");
        else        asm volatile("cp.async.wait_group 0;\n" ::: "memory");
        __syncthreads();
        if (it + 2 < 8) load_stage((it + 2) % 3, (it + 2) * 32);

        const int s = it % 3;
        const uint32_t*      As  = Ap + s * ASZ;
        const __nv_bfloat16* Bhs = Bh + s * BSZ;
        const __nv_bfloat16* Bls = Bl + s * BSZ;

#pragma unroll
        for (int ks = 0; ks < 2; ks++) {
            const int kb = ks * 16;
            uint32_t ah[2][4], al[2][4];
#pragma unroll
            for (int mt = 0; mt < 2; mt++) {
                const int row = wm * 32 + mt * 16 + g;
                uint2 p0 = *(const uint2*)&As[row * LDA + kb + qk];
                uint2 p1 = *(const uint2*)&As[(row + 8) * LDA + kb + qk];
                uint2 p2 = *(const uint2*)&As[row * LDA + kb + qk + 8];
                uint2 p3 = *(const uint2*)&As[(row + 8) * LDA + kb + qk + 8];
                ah[mt][0] = __byte_perm(p0.x, p0.y, 0x5410);
                al[mt][0] = __byte_perm(p0.x, p0.y, 0x7632);
                ah[mt][1] = __byte_perm(p1.x, p1.y, 0x5410);
                al[mt][1] = __byte_perm(p1.x, p1.y, 0x7632);
                ah[mt][2] = __byte_perm(p2.x, p2.y, 0x5410);
                al[mt][2] = __byte_perm(p2.x, p2.y, 0x7632);
                ah[mt][3] = __byte_perm(p3.x, p3.y, 0x5410);
                al[mt][3] = __byte_perm(p3.x, p3.y, 0x7632);
            }
            uint32_t bf[8][2];
#pragma unroll
            for (int nt = 0; nt < 8; nt++) {
                const __nv_bfloat16* pb = &Bhs[(wn * 64 + nt * 8 + g) * LDB + kb + qk];
                bf[nt][0] = *(const uint32_t*)pb;
                bf[nt][1] = *(const uint32_t*)(pb + 8);
            }
#pragma unroll
            for (int mt = 0; mt < 2; mt++)
#pragma unroll
                for (int nt = 0; nt < 8; nt++) {
                    mma16816(acc[mt][nt], ah[mt], bf[nt]);
                    mma16816(acc[mt][nt], al[mt], bf[nt]);
                }
#pragma unroll
            for (int nt = 0; nt < 8; nt++) {
                const __nv_bfloat16* pb = &Bls[(wn * 64 + nt * 8 + g) * LDB + kb + qk];
                bf[nt][0] = *(const uint32_t*)pb;
                bf[nt][1] = *(const uint32_t*)(pb + 8);
            }
#pragma unroll
            for (int mt = 0; mt < 2; mt++)
#pragma unroll
                for (int nt = 0; nt < 8; nt++)
                    mma16816(acc[mt][nt], ah[mt], bf[nt]);
        }
        __syncthreads();
    }

#pragma unroll
    for (int mt = 0; mt < 2; mt++) {
        const int r = m0 + wm * 32 + mt * 16 + g;
#pragma unroll
        for (int nt = 0; nt < 8; nt++) {
            const int col = wn * 64 + nt * 8 + qk;
            if constexpr (MODE == 0) {
                const float b0 = bias[col], b1 = bias[col + 1];
                *(float2*)&Cf[(size_t)r * 256 + col] =
                    make_float2(acc[mt][nt][0] + b0, acc[mt][nt][1] + b1);
                *(float2*)&Cf[(size_t)(r + 8) * 256 + col] =
                    make_float2(acc[mt][nt][2] + b0, acc[mt][nt][3] + b1);
            } else if constexpr (MODE == 1) {
                *(uint2*)&Cp[(size_t)r * 256 + col] =
                    make_uint2(pack_hilo(acc[mt][nt][0]), pack_hilo(acc[mt][nt][1]));
                *(uint2*)&Cp[(size_t)(r + 8) * 256 + col] =
                    make_uint2(pack_hilo(acc[mt][nt][2]), pack_hilo(acc[mt][nt][3]));
            } else {
                *(float2*)&Cf[(size_t)r * 256 + col] =
                    make_float2(acc[mt][nt][0], acc[mt][nt][1]);
                *(float2*)&Cf[(size_t)(r + 8) * 256 + col] =
                    make_float2(acc[mt][nt][2], acc[mt][nt][3]);
                if (col < 128) {
                    *(uint2*)&Cp[(size_t)r * 128 + col] =
                        make_uint2(pack_hilo(acc[mt][nt][0]), pack_hilo(acc[mt][nt][1]));
                    *(uint2*)&Cp[(size_t)(r + 8) * 128 + col] =
                        make_uint2(pack_hilo(acc[mt][nt][2]), pack_hilo(acc[mt][nt][3]));
                }
            }
        }
    }
}

// ---------------------------------------------------------------------------
// LN + exact GELU block helper (256 threads, channel = tid)
// ---------------------------------------------------------------------------
__device__ __forceinline__ float ln_gelu_block(
    float a, const float* __restrict__ g, const float* __restrict__ bln,
    float* red, int c)
{
    float s1 = a, s2 = a * a;
#pragma unroll
    for (int o = 16; o > 0; o >>= 1) {
        s1 += __shfl_xor_sync(0xffffffffu, s1, o);
        s2 += __shfl_xor_sync(0xffffffffu, s2, o);
    }
    if ((c & 31) == 0) { red[c >> 5] = s1; red[8 + (c >> 5)] = s2; }
    __syncthreads();
    if (c == 0) {
        float a0 = 0.f, b0 = 0.f;
#pragma unroll
        for (int i = 0; i < 8; i++) { a0 += red[i]; b0 += red[8 + i]; }
        red[0] = a0; red[8] = b0;
    }
    __syncthreads();
    const float mean = red[0] * (1.f / 256.f);
    const float var  = red[8] * (1.f / 256.f) - mean * mean;
    float y = (a - mean) * rsqrtf(var + 1e-5f) * g[c] + bln[c];
    y = 0.5f * y * (1.0f + erff(y * 0.70710678118654752f));
    __syncthreads();
    return y;
}

// ---------------------------------------------------------------------------
// Fused spatial-reduction convs: one block per branch-2 8x8 window.
// Computes 1 branch-2 token and the 4 branch-1 tokens inside it; x read once.
// Weights staged in padded smem (conflict-free broadcast-free reads).
// ---------------------------------------------------------------------------
__global__ __launch_bounds__(256) void dwconv_fused(
    const float* __restrict__ x,
    const float* __restrict__ w1, const float* __restrict__ b1c,
    const float* __restrict__ g1, const float* __restrict__ bl1,
    const float* __restrict__ w2, const float* __restrict__ b2c,
    const float* __restrict__ g2, const float* __restrict__ bl2,
    uint32_t* __restrict__ x1p, uint32_t* __restrict__ x2p)
{
    extern __shared__ float sw[];
    float* w2s = sw;                 // [64][257]
    float* w1s = sw + 64 * 257;      // [16][257]
    float* red = sw + 80 * 257;      // [16]

    const int tid = threadIdx.x, c = tid;
    const int b = blockIdx.x >> 6;
    const int t2 = blockIdx.x & 63;
    const int oh2 = t2 >> 3, ow2 = t2 & 7;

    // stage weights transposed: coalesced global, padded smem stores
#pragma unroll 8
    for (int i = 0; i < 64; i++) {
        const int gidx = i * 256 + tid;
        w2s[(gidx & 63) * 257 + (gidx >> 6)] = w2[gidx];
    }
#pragma unroll
    for (int i = 0; i < 16; i++) {
        const int gidx = i * 256 + tid;
        w1s[(gidx & 15) * 257 + (gidx >> 4)] = w1[gidx];
    }
    __syncthreads();

    float acc2 = b2c[c];
    float acc1[2][2];
    acc1[0][0] = acc1[0][1] = acc1[1][0] = acc1[1][1] = b1c[c];

#pragma unroll
    for (int kh = 0; kh < 8; kh++) {
#pragma unroll
        for (int kw = 0; kw < 8; kw++) {
            const int ih = oh2 * 8 + kh, iw = ow2 * 8 + kw;
            const float xv = x[((size_t)b * NTOK + ih * 64 + iw) * CH + c];
            acc2 += xv * w2s[(kh * 8 + kw) * 257 + c];
            acc1[kh >> 2][kw >> 2] += xv * w1s[((kh & 3) * 4 + (kw & 3)) * 257 + c];
        }
    }

    const float y2 = ln_gelu_block(acc2, g2, bl2, red, c);
    x2p[((size_t)b * 64 + t2) * CH + c] = pack_hilo(y2);
#pragma unroll
    for (int i = 0; i < 2; i++)
#pragma unroll
        for (int j = 0; j < 2; j++) {
            const float y1 = ln_gelu_block(acc1[i][j], g1, bl1, red, c);
            const int t1 = (oh2 * 2 + i) * 16 + (ow2 * 2 + j);
            x1p[((size_t)b * 256 + t1) * CH + c] = pack_hilo(y1);
        }
}

// ---------------------------------------------------------------------------
// Fused v local conv (+residual) -> packed V^T [b,h][e][s]; both branches.
// ---------------------------------------------------------------------------
__global__ __launch_bounds__(128) void vconv_fused(
    const float* __restrict__ kv1, const float* __restrict__ lcw1,
    const float* __restrict__ lcb1, uint32_t* __restrict__ v1p,
    const float* __restrict__ kv2, const float* __restrict__ lcw2,
    const float* __restrict__ lcb2, uint32_t* __restrict__ v2p)
{
    int token, HS;
    const float *kv, *lcw, *lcb;
    uint32_t* vtp;
    if (blockIdx.x < BATCH * 256) {
        token = blockIdx.x; HS = 16; kv = kv1; lcw = lcw1; lcb = lcb1; vtp = v1p;
    } else {
        token = blockIdx.x - BATCH * 256; HS = 8; kv = kv2; lcw = lcw2; lcb = lcb2; vtp = v2p;
    }
    const int NS = HS * HS;
    const int b  = token / NS;
    const int s  = token - b * NS;
    const int hs = s / HS, ws = s - hs * HS;
    const int c  = threadIdx.x;

    float acc = lcb[c];
#pragma unroll
    for (int kh = 0; kh < 3; kh++)
#pragma unroll
        for (int kw = 0; kw < 3; kw++) {
            const int ih = hs - 1 + kh, iw = ws - 1 + kw;
            if (ih >= 0 && ih < HS && iw >= 0 && iw < HS)
                acc += kv[((size_t)b * NS + ih * HS + iw) * 256 + 128 + c]
                     * lcw[c * 9 + kh * 3 + kw];
        }
    const float v = kv[(size_t)token * 256 + 128 + c] + acc;
    const int h = c >> 5, e = c & 31;
    vtp[(((size_t)b * 4 + h) * 32 + e) * NS + s] = pack_hilo(v);
}

// ---------------------------------------------------------------------------
// Attention via mma (verified round-4 math); epilogue now writes packed cat.
// ---------------------------------------------------------------------------
template<int NS>
__global__ __launch_bounds__(256) void attn_mma(
    const uint32_t* __restrict__ qp,   // [B*4096][256]
    const uint32_t* __restrict__ kp,   // [B*NS][128]
    const uint32_t* __restrict__ vtp,  // [B*4][32][NS]
    uint32_t* __restrict__ catp,       // [B*4096][256] packed
    int qoff, int ooff)
{
    constexpr int NSP = NS + 2;
    constexpr int LDQ = 34;
    constexpr int NT  = NS / 32;
    constexpr int LOG = (NS == 256) ? 8 : 6;
    const float scale = 0.17677669529663689f;

    extern __shared__ float smf[];
    uint32_t* Qs = (uint32_t*)smf;
    uint32_t* Ks = Qs + 64 * LDQ;
    float*    Ss = (float*)(Ks + NS * LDQ);
    float*    rs = Ss + 64 * NSP;
    uint32_t* Vs = Ks;
    uint32_t* Sp = (uint32_t*)Ss;

    const int b = blockIdx.x >> 2, h = blockIdx.x & 3;
    const int q0 = blockIdx.y * 64;
    const int tid = threadIdx.x, lane = tid & 31, w = tid >> 5;
    const int g = lane >> 2, qk = (lane & 3) * 2;

    for (int i = tid; i < 64 * 32; i += 256) {
        const int r = i >> 5, e = i & 31;
        Qs[r * LDQ + e] = qp[((size_t)(b * 4096 + q0 + r)) * 256 + qoff + h * 32 + e];
    }
    for (int i = tid; i < NS * 32; i += 256) {
        const int s = i >> 5, e = i & 31;
        Ks[s * LDQ + e] = kp[((size_t)(b * NS + s)) * 128 + h * 32 + e];
    }
    __syncthreads();

    // phase 1: S = Q K^T
    {
        const int wm = w & 1, wn = w >> 1;
        float acc[2][NT][4];
#pragma unroll
        for (int mt = 0; mt < 2; mt++)
#pragma unroll
            for (int nt = 0; nt < NT; nt++)
#pragma unroll
                for (int r = 0; r < 4; r++) acc[mt][nt][r] = 0.f;

#pragma unroll
        for (int kc = 0; kc < 2; kc++) {
            const int kb = kc * 16;
            uint32_t ah[2][4], al[2][4];
#pragma unroll
            for (int mt = 0; mt < 2; mt++) {
                const int row = wm * 32 + mt * 16 + g;
                uint2 p0 = *(const uint2*)&Qs[row * LDQ + kb + qk];
                uint2 p1 = *(const uint2*)&Qs[(row + 8) * LDQ + kb + qk];
                uint2 p2 = *(const uint2*)&Qs[row * LDQ + kb + qk + 8];
                uint2 p3 = *(const uint2*)&Qs[(row + 8) * LDQ + kb + qk + 8];
                ah[mt][0] = __byte_perm(p0.x, p0.y, 0x5410);
                al[mt][0] = __byte_perm(p0.x, p0.y, 0x7632);
                ah[mt][1] = __byte_perm(p1.x, p1.y, 0x5410);
                al[mt][1] = __byte_perm(p1.x, p1.y, 0x7632);
                ah[mt][2] = __byte_perm(p2.x, p2.y, 0x5410);
                al[mt][2] = __byte_perm(p2.x, p2.y, 0x7632);
                ah[mt][3] = __byte_perm(p3.x, p3.y, 0x5410);
                al[mt][3] = __byte_perm(p3.x, p3.y, 0x7632);
            }
            uint32_t bh[NT][2], bl[NT][2];
#pragma unroll
            for (int nt = 0; nt < NT; nt++) {
                const int srow = wn * (NS / 4) + nt * 8 + g;
                uint2 p0 = *(const uint2*)&Ks[srow * LDQ + kb + qk];
                uint2 p1 = *(const uint2*)&Ks[srow * LDQ + kb + qk + 8];
                bh[nt][0] = __byte_perm(p0.x, p0.y, 0x5410);
                bl[nt][0] = __byte_perm(p0.x, p0.y, 0x7632);
                bh[nt][1] = __byte_perm(p1.x, p1.y, 0x5410);
                bl[nt][1] = __byte_perm(p1.x, p1.y, 0x7632);
            }
#pragma unroll
            for (int mt = 0; mt < 2; mt++)
#pragma unroll
                for (int nt = 0; nt < NT; nt++) {
                    mma16816(acc[mt][nt], ah[mt], bh[nt]);
                    mma16816(acc[mt][nt], al[mt], bh[nt]);
                    mma16816(acc[mt][nt], ah[mt], bl[nt]);
                }
        }
#pragma unroll
        for (int mt = 0; mt < 2; mt++) {
            const int r = wm * 32 + mt * 16 + g;
#pragma unroll
            for (int nt = 0; nt < NT; nt++) {
                const int col = wn * (NS / 4) + nt * 8 + qk;
                *(float2*)&Ss[r * NSP + col] =
                    make_float2(acc[mt][nt][0] * scale, acc[mt][nt][1] * scale);
                *(float2*)&Ss[(r + 8) * NSP + col] =
                    make_float2(acc[mt][nt][2] * scale, acc[mt][nt][3] * scale);
            }
        }
    }
    __syncthreads();

    // stage V^T (overwrites Ks)
    for (int i = tid; i < 32 * NS; i += 256) {
        const int e = i >> LOG, s = i & (NS - 1);
        Vs[e * NSP + s] = vtp[(((size_t)(b * 4 + h)) * 32 + e) * NS + s];
    }

    // softmax + pack in place
    {
        constexpr int JN = NS / 32;
#pragma unroll
        for (int i = 0; i < 8; i++) {
            const int r = w * 8 + i;
            float v[JN];
            float mx = -1e30f;
#pragma unroll
            for (int j = 0; j < JN; j++) {
                v[j] = Ss[r * NSP + lane + j * 32];
                mx = fmaxf(mx, v[j]);
            }
#pragma unroll
            for (int o = 16; o > 0; o >>= 1)
                mx = fmaxf(mx, __shfl_xor_sync(0xffffffffu, mx, o));
            float sum = 0.f;
#pragma unroll
            for (int j = 0; j < JN; j++) { v[j] = __expf(v[j] - mx); sum += v[j]; }
#pragma unroll
            for (int o = 16; o > 0; o >>= 1)
                sum += __shfl_xor_sync(0xffffffffu, sum, o);
#pragma unroll
            for (int j = 0; j < JN; j++)
                Sp[r * NSP + lane + j * 32] = pack_hilo(v[j]);
            if (lane == 0) rs[r] = sum;
        }
    }
    __syncthreads();

    // phase 3: O = P V
    {
        const int wm = w & 3, wn = w >> 2;
        float acc[2][4];
#pragma unroll
        for (int nt = 0; nt < 2; nt++)
#pragma unroll
            for (int r = 0; r < 4; r++) acc[nt][r] = 0.f;

#pragma unroll 4
        for (int kc = 0; kc < NS / 16; kc++) {
            const int kb = kc * 16;
            const int row = wm * 16 + g;
            uint32_t ah[4], al[4];
            {
                uint2 p0 = *(const uint2*)&Sp[row * NSP + kb + qk];
                uint2 p1 = *(const uint2*)&Sp[(row + 8) * NSP + kb + qk];
                uint2 p2 = *(const uint2*)&Sp[row * NSP + kb + qk + 8];
                uint2 p3 = *(const uint2*)&Sp[(row + 8) * NSP + kb + qk + 8];
                ah[0] = __byte_perm(p0.x, p0.y, 0x5410);
                al[0] = __byte_perm(p0.x, p0.y, 0x7632);
                ah[1] = __byte_perm(p1.x, p1.y, 0x5410);
                al[1] = __byte_perm(p1.x, p1.y, 0x7632);
                ah[2] = __byte_perm(p2.x, p2.y, 0x5410);
                al[2] = __byte_perm(p2.x, p2.y, 0x7632);
                ah[3] = __byte_perm(p3.x, p3.y, 0x5410);
                al[3] = __byte_perm(p3.x, p3.y, 0x7632);
            }
            uint32_t bh[2][2], bl[2][2];
#pragma unroll
            for (int nt = 0; nt < 2; nt++) {
                const int e = wn * 16 + nt * 8 + g;
                uint2 p0 = *(const uint2*)&Vs[e * NSP + kb + qk];
                uint2 p1 = *(const uint2*)&Vs[e * NSP + kb + qk + 8];
                bh[nt][0] = __byte_perm(p0.x, p0.y, 0x5410);
                bl[nt][0] = __byte_perm(p0.x, p0.y, 0x7632);
                bh[nt][1] = __byte_perm(p1.x, p1.y, 0x5410);
                bl[nt][1] = __byte_perm(p1.x, p1.y, 0x7632);
            }
#pragma unroll
            for (int nt = 0; nt < 2; nt++) {
                mma16816(acc[nt], ah, bh[nt]);
                mma16816(acc[nt], al, bh[nt]);
                mma16816(acc[nt], ah, bl[nt]);
            }
        }

        const int r0 = wm * 16 + g;
        const float inv0 = 1.0f / rs[r0];
        const float inv1 = 1.0f / rs[r0 + 8];
#pragma unroll
        for (int nt = 0; nt < 2; nt++) {
            const int col = ooff + h * 32 + wn * 16 + nt * 8 + qk;
            *(uint2*)&catp[((size_t)(b * 4096 + q0 + r0)) * 256 + col] =
                make_uint2(pack_hilo(acc[nt][0] * inv0), pack_hilo(acc[nt][1] * inv0));
            *(uint2*)&catp[((size_t)(b * 4096 + q0 + r0 + 8)) * 256 + col] =
                make_uint2(pack_hilo(acc[nt][2] * inv1), pack_hilo(acc[nt][3] * inv1));
        }
    }
}

// ---------------------------------------------------------------------------
// launch
// ---------------------------------------------------------------------------
extern "C" void kernel_launch(void* const* d_in, const int* in_sizes, int n_in,
                              void* d_out, int out_size)
{
    const float* x      = (const float*)d_in[0];
    const float* q_w    = (const float*)d_in[1];
    const float* kv1_w  = (const float*)d_in[2];
    const float* kv2_w  = (const float*)d_in[3];
    const float* proj_w = (const float*)d_in[4];
    const float* proj_b = (const float*)d_in[5];
    const float* sr1_w  = (const float*)d_in[6];
    const float* sr1_b  = (const float*)d_in[7];
    const float* sr2_w  = (const float*)d_in[8];
    const float* sr2_b  = (const float*)d_in[9];
    const float* ln1_g  = (const float*)d_in[10];
    const float* ln1_b  = (const float*)d_in[11];
    const float* ln2_g  = (const float*)d_in[12];
    const float* ln2_b  = (const float*)d_in[13];
    const float* lc1_w  = (const float*)d_in[14];
    const float* lc1_b  = (const float*)d_in[15];
    const float* lc2_w  = (const float*)d_in[16];
    const float* lc2_b  = (const float*)d_in[17];
    float* out = (float*)d_out;

    uint32_t *p_xp, *p_qp, *p_catp, *p_x1p, *p_x2p, *p_k1p, *p_k2p, *p_v1p, *p_v2p;
    float *p_kv1, *p_kv2;
    __nv_bfloat16 *p_qwh, *p_qwl, *p_k1wh, *p_k1wl, *p_k2wh, *p_k2wl, *p_pwh, *p_pwl;
    cudaGetSymbolAddress((void**)&p_xp,   g_xp);
    cudaGetSymbolAddress((void**)&p_qp,   g_qp);
    cudaGetSymbolAddress((void**)&p_catp, g_catp);
    cudaGetSymbolAddress((void**)&p_x1p,  g_x1p);
    cudaGetSymbolAddress((void**)&p_x2p,  g_x2p);
    cudaGetSymbolAddress((void**)&p_kv1,  g_kv1);
    cudaGetSymbolAddress((void**)&p_kv2,  g_kv2);
    cudaGetSymbolAddress((void**)&p_k1p,  g_k1p);
    cudaGetSymbolAddress((void**)&p_k2p,  g_k2p);
    cudaGetSymbolAddress((void**)&p_v1p,  g_v1p);
    cudaGetSymbolAddress((void**)&p_v2p,  g_v2p);
    cudaGetSymbolAddress((void**)&p_qwh,  g_qwh);
    cudaGetSymbolAddress((void**)&p_qwl,  g_qwl);
    cudaGetSymbolAddress((void**)&p_k1wh, g_k1wh);
    cudaGetSymbolAddress((void**)&p_k1wl, g_k1wl);
    cudaGetSymbolAddress((void**)&p_k2wh, g_k2wh);
    cudaGetSymbolAddress((void**)&p_k2wl, g_k2wl);
    cudaGetSymbolAddress((void**)&p_pwh,  g_pwh);
    cudaGetSymbolAddress((void**)&p_pwl,  g_pwl);

    // dynamic smem sizes
    const int smem_gemm = 3 * (128 * 40 * 4) + 2 * (3 * 256 * 40 * 2);  // 184,320
    const int smem_dw   = 80 * 257 * 4 + 64;                            //  82,304
    const int smem_a1   = (64 * 34 + 256 * 34) * 4 + 64 * 258 * 4 + 64 * 4;
    const int smem_a2   = (64 * 34 + 64 * 34) * 4 + 64 * 66 * 4 + 64 * 4;
    cudaFuncSetAttribute(gemm_pk<0>, cudaFuncAttributeMaxDynamicSharedMemorySize, smem_gemm);
    cudaFuncSetAttribute(gemm_pk<1>, cudaFuncAttributeMaxDynamicSharedMemorySize, smem_gemm);
    cudaFuncSetAttribute(gemm_pk<2>, cudaFuncAttributeMaxDynamicSharedMemorySize, smem_gemm);
    cudaFuncSetAttribute(dwconv_fused, cudaFuncAttributeMaxDynamicSharedMemorySize, smem_dw);
    cudaFuncSetAttribute(attn_mma<256>, cudaFuncAttributeMaxDynamicSharedMemorySize, smem_a1);
    cudaFuncSetAttribute(attn_mma<64>,  cudaFuncAttributeMaxDynamicSharedMemorySize, smem_a2);

    // 1. weight splits
    split_wgt4<<<1024, 256>>>(q_w, kv1_w, kv2_w, proj_w,
                              p_qwh, p_qwl, p_k1wh, p_k1wl,
                              p_k2wh, p_k2wl, p_pwh, p_pwl);
    // 2. x -> packed
    split_x<<<(BATCH * NTOK * CH) / 1024, 256>>>(x, p_xp);
    // 3. q projection -> packed
    gemm_pk<1><<<256, 512, smem_gemm>>>(p_xp, p_qwh, p_qwl, nullptr, nullptr, p_qp);
    // 4. fused spatial-reduction convs -> packed x1/x2
    dwconv_fused<<<BATCH * 64, 256, smem_dw>>>(
        x, sr1_w, sr1_b, ln1_g, ln1_b, sr2_w, sr2_b, ln2_g, ln2_b, p_x1p, p_x2p);
    // 5/6. kv projections -> fp32 kv + packed k
    gemm_pk<2><<<16, 512, smem_gemm>>>(p_x1p, p_k1wh, p_k1wl, nullptr, p_kv1, p_k1p);
    gemm_pk<2><<<4,  512, smem_gemm>>>(p_x2p, p_k2wh, p_k2wl, nullptr, p_kv2, p_k2p);
    // 7. fused v local conv -> packed V^T
    vconv_fused<<<BATCH * 256 + BATCH * 64, 128>>>(
        p_kv1, lc1_w, lc1_b, p_v1p, p_kv2, lc2_w, lc2_b, p_v2p);
    // 8/9. attention -> packed cat
    attn_mma<256><<<dim3(32, 64), 256, smem_a1>>>(p_qp, p_k1p, p_v1p, p_catp, 0,   0);
    attn_mma<64 ><<<dim3(32, 64), 256, smem_a2>>>(p_qp, p_k2p, p_v2p, p_catp, 128, 128);
    // 10. output projection
    gemm_pk<0><<<256, 512, smem_gemm>>>(p_catp, p_pwh, p_pwl, proj_b, out, nullptr);
}

// round 6
// speedup vs baseline: 2.1777x; 1.0974x over previous
#include <cuda_runtime.h>
#include <cuda_bf16.h>
#include <cstdint>

// Problem constants: B=8, H=W=64, N=4096, C=256, nh=8, nh2=4, hd=32, sr=8
#define BATCH 8
#define NTOK 4096
#define CH 256

// ---------------------------------------------------------------------------
// Scratch (device globals)
// ---------------------------------------------------------------------------
__device__ uint32_t g_xp  [(size_t)BATCH * NTOK * CH];   // x packed (hi,lo)
__device__ uint32_t g_qp  [(size_t)BATCH * NTOK * CH];   // q packed
__device__ uint32_t g_catp[(size_t)BATCH * NTOK * CH];   // cat packed
__device__ uint32_t g_x1p [BATCH * 256 * CH];
__device__ uint32_t g_x2p [BATCH * 64 * CH];
__device__ float    g_kv1 [BATCH * 256 * CH];
__device__ float    g_kv2 [BATCH * 64 * CH];
__device__ uint32_t g_k1p [BATCH * 256 * 128];
__device__ uint32_t g_k2p [BATCH * 64 * 128];
__device__ uint32_t g_v1p [BATCH * 4 * 32 * 256];        // V^T packed [b,h][e][s]
__device__ uint32_t g_v2p [BATCH * 4 * 32 * 64];
// weight splits
__device__ __nv_bfloat16 g_qwh [256 * 256], g_qwl [256 * 256];
__device__ __nv_bfloat16 g_k1wh[256 * 256], g_k1wl[256 * 256];
__device__ __nv_bfloat16 g_k2wh[256 * 256], g_k2wl[256 * 256];
__device__ __nv_bfloat16 g_pwh [256 * 256], g_pwl [256 * 256];

// ---------------------------------------------------------------------------
// helpers
// ---------------------------------------------------------------------------
__device__ __forceinline__ uint32_t pack_hilo(float v) {
    __nv_bfloat16 h = __float2bfloat16(v);
    __nv_bfloat16 l = __float2bfloat16(v - __bfloat162float(h));
    return (uint32_t)__bfloat16_as_ushort(h) |
           ((uint32_t)__bfloat16_as_ushort(l) << 16);
}

__device__ __forceinline__ void mma16816(
    float* c, const uint32_t* a, const uint32_t* b)
{
    asm volatile(
        "mma.sync.aligned.m16n8k16.row.col.f32.bf16.bf16.f32 "
        "{%0,%1,%2,%3}, {%4,%5,%6,%7}, {%8,%9}, {%0,%1,%2,%3};"
        : "+f"(c[0]), "+f"(c[1]), "+f"(c[2]), "+f"(c[3])
        : "r"(a[0]), "r"(a[1]), "r"(a[2]), "r"(a[3]), "r"(b[0]), "r"(b[1]));
}

__device__ __forceinline__ void cpa16(void* dst, const void* src) {
    uint32_t d = (uint32_t)__cvta_generic_to_shared(dst);
    asm volatile("cp.async.cg.shared.global [%0], [%1], 16;\n"
                 :: "r"(d), "l"(src));
}

// ---------------------------------------------------------------------------
// Combined split: blocks [0,1024) split 4 weight matrices (hi/lo separate),
// blocks [1024,9216) split x fp32 -> packed u32.
// ---------------------------------------------------------------------------
__global__ __launch_bounds__(256) void split_all(
    const float* __restrict__ x, uint32_t* __restrict__ xp,
    const float* __restrict__ w0, const float* __restrict__ w1,
    const float* __restrict__ w2, const float* __restrict__ w3,
    __nv_bfloat16* __restrict__ h0, __nv_bfloat16* __restrict__ l0,
    __nv_bfloat16* __restrict__ h1, __nv_bfloat16* __restrict__ l1,
    __nv_bfloat16* __restrict__ h2, __nv_bfloat16* __restrict__ l2,
    __nv_bfloat16* __restrict__ h3, __nv_bfloat16* __restrict__ l3)
{
    if (blockIdx.x < 1024) {
        const int which = blockIdx.x >> 8;
        const int i = (blockIdx.x & 255) * 256 + threadIdx.x;
        const float* in = which == 0 ? w0 : which == 1 ? w1 : which == 2 ? w2 : w3;
        __nv_bfloat16* oh = which == 0 ? h0 : which == 1 ? h1 : which == 2 ? h2 : h3;
        __nv_bfloat16* ol = which == 0 ? l0 : which == 1 ? l1 : which == 2 ? l2 : l3;
        const float v = in[i];
        const __nv_bfloat16 hi = __float2bfloat16(v);
        oh[i] = hi;
        ol[i] = __float2bfloat16(v - __bfloat162float(hi));
    } else {
        const size_t i = ((size_t)(blockIdx.x - 1024) * 256 + threadIdx.x) * 4;
        float4 v = *(const float4*)&x[i];
        *(uint4*)&xp[i] = make_uint4(pack_hilo(v.x), pack_hilo(v.y),
                                     pack_hilo(v.z), pack_hilo(v.w));
    }
}

// ---------------------------------------------------------------------------
// Pipelined tensor-core GEMM body. C[m,n] = sum_k A[m,k]*W[n,k]; K=256, N=256.
// A packed u32 [M,256]; W split Whi/Wlo bf16 [256,256].
// 3-term split: ah*wh + al*wh + ah*wl. 512 threads, 3-stage cp.async.
// MODE 0: fp32 out (+bias). MODE 1: packed out. MODE 2: fp32 + packed k-half.
// ---------------------------------------------------------------------------
template<int MODE>
__device__ __forceinline__ void gemm_body(
    const uint32_t* __restrict__ A,
    const __nv_bfloat16* __restrict__ Wh,
    const __nv_bfloat16* __restrict__ Wl,
    const float* __restrict__ bias,
    float* __restrict__ Cf, uint32_t* __restrict__ Cp,
    int m0, char* smraw)
{
    constexpr int LDA = 40;
    constexpr int LDB = 40;
    constexpr int ASZ = 128 * LDA;
    constexpr int BSZ = 256 * LDB;

    uint32_t*      Ap = (uint32_t*)smraw;                 // [3][128][LDA]
    __nv_bfloat16* Bh = (__nv_bfloat16*)(Ap + 3 * ASZ);   // [3][256][LDB]
    __nv_bfloat16* Bl = Bh + 3 * BSZ;                     // [3][256][LDB]

    const int tid = threadIdx.x;
    const int w = tid >> 5, lane = tid & 31;
    const int wm = w & 3, wn = w >> 2;          // 4 x 4 warps, 32x64 tile
    const int g = lane >> 2, qk = (lane & 3) * 2;

    auto load_stage = [&](int s, int k0) {
#pragma unroll
        for (int i = 0; i < 2; i++) {
            const int c = tid + i * 512;
            const int row = c >> 3, ch = c & 7;
            cpa16(&Ap[s * ASZ + row * LDA + ch * 4],
                  &A[(size_t)(m0 + row) * 256 + k0 + ch * 4]);
        }
#pragma unroll
        for (int i = 0; i < 2; i++) {
            const int c = tid + i * 512;
            const int row = c >> 2, ch = c & 3;
            cpa16(&Bh[s * BSZ + row * LDB + ch * 8],
                  &Wh[(size_t)row * 256 + k0 + ch * 8]);
        }
#pragma unroll
        for (int i = 0; i < 2; i++) {
            const int c = tid + i * 512;
            const int row = c >> 2, ch = c & 3;
            cpa16(&Bl[s * BSZ + row * LDB + ch * 8],
                  &Wl[(size_t)row * 256 + k0 + ch * 8]);
        }
        asm volatile("cp.async.commit_group;\n" ::: "memory");
    };

    float acc[2][8][4];
#pragma unroll
    for (int mt = 0; mt < 2; mt++)
#pragma unroll
        for (int nt = 0; nt < 8; nt++)
#pragma unroll
            for (int r = 0; r < 4; r++) acc[mt][nt][r] = 0.f;

    load_stage(0, 0);
    load_stage(1, 32);

    for (int it = 0; it < 8; it++) {
        if (it < 7) asm volatile("cp.async.wait_group 1;\n" ::: "memory");
        else        asm volatile("cp.async.wait_group 0;\n" ::: "memory");
        __syncthreads();
        if (it + 2 < 8) load_stage((it + 2) % 3, (it + 2) * 32);

        const int s = it % 3;
        const uint32_t*      As  = Ap + s * ASZ;
        const __nv_bfloat16* Bhs = Bh + s * BSZ;
        const __nv_bfloat16* Bls = Bl + s * BSZ;

#pragma unroll
        for (int ks = 0; ks < 2; ks++) {
            const int kb = ks * 16;
            uint32_t ah[2][4], al[2][4];
#pragma unroll
            for (int mt = 0; mt < 2; mt++) {
                const int row = wm * 32 + mt * 16 + g;
                uint2 p0 = *(const uint2*)&As[row * LDA + kb + qk];
                uint2 p1 = *(const uint2*)&As[(row + 8) * LDA + kb + qk];
                uint2 p2 = *(const uint2*)&As[row * LDA + kb + qk + 8];
                uint2 p3 = *(const uint2*)&As[(row + 8) * LDA + kb + qk + 8];
                ah[mt][0] = __byte_perm(p0.x, p0.y, 0x5410);
                al[mt][0] = __byte_perm(p0.x, p0.y, 0x7632);
                ah[mt][1] = __byte_perm(p1.x, p1.y, 0x5410);
                al[mt][1] = __byte_perm(p1.x, p1.y, 0x7632);
                ah[mt][2] = __byte_perm(p2.x, p2.y, 0x5410);
                al[mt][2] = __byte_perm(p2.x, p2.y, 0x7632);
                ah[mt][3] = __byte_perm(p3.x, p3.y, 0x5410);
                al[mt][3] = __byte_perm(p3.x, p3.y, 0x7632);
            }
            uint32_t bf[8][2];
#pragma unroll
            for (int nt = 0; nt < 8; nt++) {
                const __nv_bfloat16* pb = &Bhs[(wn * 64 + nt * 8 + g) * LDB + kb + qk];
                bf[nt][0] = *(const uint32_t*)pb;
                bf[nt][1] = *(const uint32_t*)(pb + 8);
            }
#pragma unroll
            for (int mt = 0; mt < 2; mt++)
#pragma unroll
                for (int nt = 0; nt < 8; nt++) {
                    mma16816(acc[mt][nt], ah[mt], bf[nt]);
                    mma16816(acc[mt][nt], al[mt], bf[nt]);
                }
#pragma unroll
            for (int nt = 0; nt < 8; nt++) {
                const __nv_bfloat16* pb = &Bls[(wn * 64 + nt * 8 + g) * LDB + kb + qk];
                bf[nt][0] = *(const uint32_t*)pb;
                bf[nt][1] = *(const uint32_t*)(pb + 8);
            }
#pragma unroll
            for (int mt = 0; mt < 2; mt++)
#pragma unroll
                for (int nt = 0; nt < 8; nt++)
                    mma16816(acc[mt][nt], ah[mt], bf[nt]);
        }
        __syncthreads();
    }

#pragma unroll
    for (int mt = 0; mt < 2; mt++) {
        const int r = m0 + wm * 32 + mt * 16 + g;
#pragma unroll
        for (int nt = 0; nt < 8; nt++) {
            const int col = wn * 64 + nt * 8 + qk;
            if constexpr (MODE == 0) {
                const float b0 = bias[col], b1 = bias[col + 1];
                *(float2*)&Cf[(size_t)r * 256 + col] =
                    make_float2(acc[mt][nt][0] + b0, acc[mt][nt][1] + b1);
                *(float2*)&Cf[(size_t)(r + 8) * 256 + col] =
                    make_float2(acc[mt][nt][2] + b0, acc[mt][nt][3] + b1);
            } else if constexpr (MODE == 1) {
                *(uint2*)&Cp[(size_t)r * 256 + col] =
                    make_uint2(pack_hilo(acc[mt][nt][0]), pack_hilo(acc[mt][nt][1]));
                *(uint2*)&Cp[(size_t)(r + 8) * 256 + col] =
                    make_uint2(pack_hilo(acc[mt][nt][2]), pack_hilo(acc[mt][nt][3]));
            } else {
                *(float2*)&Cf[(size_t)r * 256 + col] =
                    make_float2(acc[mt][nt][0], acc[mt][nt][1]);
                *(float2*)&Cf[(size_t)(r + 8) * 256 + col] =
                    make_float2(acc[mt][nt][2], acc[mt][nt][3]);
                if (col < 128) {
                    *(uint2*)&Cp[(size_t)r * 128 + col] =
                        make_uint2(pack_hilo(acc[mt][nt][0]), pack_hilo(acc[mt][nt][1]));
                    *(uint2*)&Cp[(size_t)(r + 8) * 128 + col] =
                        make_uint2(pack_hilo(acc[mt][nt][2]), pack_hilo(acc[mt][nt][3]));
                }
            }
        }
    }
}

template<int MODE>
__global__ __launch_bounds__(512) void gemm_pk(
    const uint32_t* __restrict__ A,
    const __nv_bfloat16* __restrict__ Wh,
    const __nv_bfloat16* __restrict__ Wl,
    const float* __restrict__ bias,
    float* __restrict__ Cf, uint32_t* __restrict__ Cp)
{
    extern __shared__ __align__(16) char smraw[];
    gemm_body<MODE>(A, Wh, Wl, bias, Cf, Cp, blockIdx.x * 128, smraw);
}

// Combined kv gemms: blocks [0,16) branch1, [16,20) branch2. MODE 2.
__global__ __launch_bounds__(512) void gemm_kv(
    const uint32_t* __restrict__ A1, const uint32_t* __restrict__ A2,
    const __nv_bfloat16* __restrict__ Wh1, const __nv_bfloat16* __restrict__ Wl1,
    const __nv_bfloat16* __restrict__ Wh2, const __nv_bfloat16* __restrict__ Wl2,
    float* __restrict__ kv1, float* __restrict__ kv2,
    uint32_t* __restrict__ k1p, uint32_t* __restrict__ k2p)
{
    extern __shared__ __align__(16) char smraw[];
    if (blockIdx.x < 16)
        gemm_body<2>(A1, Wh1, Wl1, nullptr, kv1, k1p, blockIdx.x * 128, smraw);
    else
        gemm_body<2>(A2, Wh2, Wl2, nullptr, kv2, k2p, (blockIdx.x - 16) * 128, smraw);
}

// ---------------------------------------------------------------------------
// LN + exact GELU block helper (per-window; 256 channels, c = tid&255)
// ---------------------------------------------------------------------------
__device__ __forceinline__ float ln_gelu_block(
    float a, const float* __restrict__ g, const float* __restrict__ bln,
    float* red, int c)
{
    float s1 = a, s2 = a * a;
#pragma unroll
    for (int o = 16; o > 0; o >>= 1) {
        s1 += __shfl_xor_sync(0xffffffffu, s1, o);
        s2 += __shfl_xor_sync(0xffffffffu, s2, o);
    }
    if ((c & 31) == 0) { red[c >> 5] = s1; red[8 + (c >> 5)] = s2; }
    __syncthreads();
    if (c == 0) {
        float a0 = 0.f, b0 = 0.f;
#pragma unroll
        for (int i = 0; i < 8; i++) { a0 += red[i]; b0 += red[8 + i]; }
        red[0] = a0; red[8] = b0;
    }
    __syncthreads();
    const float mean = red[0] * (1.f / 256.f);
    const float var  = red[8] * (1.f / 256.f) - mean * mean;
    float y = (a - mean) * rsqrtf(var + 1e-5f) * g[c] + bln[c];
    y = 0.5f * y * (1.0f + erff(y * 0.70710678118654752f));
    __syncthreads();
    return y;
}

// ---------------------------------------------------------------------------
// Fused spatial-reduction convs: 512 threads, TWO adjacent 8x8 windows per
// block sharing staged weights (halves staging, doubles occupancy).
// ---------------------------------------------------------------------------
__global__ __launch_bounds__(512) void dwconv_fused(
    const float* __restrict__ x,
    const float* __restrict__ w1, const float* __restrict__ b1c,
    const float* __restrict__ g1, const float* __restrict__ bl1,
    const float* __restrict__ w2, const float* __restrict__ b2c,
    const float* __restrict__ g2, const float* __restrict__ bl2,
    uint32_t* __restrict__ x1p, uint32_t* __restrict__ x2p)
{
    extern __shared__ float sw[];
    float* w2s = sw;                 // [64][257]
    float* w1s = sw + 64 * 257;      // [16][257]
    float* redb = sw + 80 * 257;     // [2][16]

    const int tid = threadIdx.x;
    const int c = tid & 255;
    const int win = tid >> 8;
    float* red = redb + win * 16;

    const int b = blockIdx.x >> 5;
    const int pair = blockIdx.x & 31;
    const int t2 = pair * 2 + win;
    const int oh2 = t2 >> 3, ow2 = t2 & 7;

    // stage weights transposed: coalesced global, padded smem
    for (int i = tid; i < 64 * 256; i += 512)
        w2s[(i & 63) * 257 + (i >> 6)] = w2[i];
    for (int i = tid; i < 16 * 256; i += 512)
        w1s[(i & 15) * 257 + (i >> 4)] = w1[i];
    __syncthreads();

    float acc2 = b2c[c];
    float acc1[2][2];
    acc1[0][0] = acc1[0][1] = acc1[1][0] = acc1[1][1] = b1c[c];

#pragma unroll
    for (int kh = 0; kh < 8; kh++) {
#pragma unroll
        for (int kw = 0; kw < 8; kw++) {
            const int ih = oh2 * 8 + kh, iw = ow2 * 8 + kw;
            const float xv = x[((size_t)b * NTOK + ih * 64 + iw) * CH + c];
            acc2 += xv * w2s[(kh * 8 + kw) * 257 + c];
            acc1[kh >> 2][kw >> 2] += xv * w1s[((kh & 3) * 4 + (kw & 3)) * 257 + c];
        }
    }

    const float y2 = ln_gelu_block(acc2, g2, bl2, red, c);
    x2p[((size_t)b * 64 + t2) * CH + c] = pack_hilo(y2);
#pragma unroll
    for (int i = 0; i < 2; i++)
#pragma unroll
        for (int j = 0; j < 2; j++) {
            const float y1 = ln_gelu_block(acc1[i][j], g1, bl1, red, c);
            const int t1 = (oh2 * 2 + i) * 16 + (ow2 * 2 + j);
            x1p[((size_t)b * 256 + t1) * CH + c] = pack_hilo(y1);
        }
}

// ---------------------------------------------------------------------------
// Fused v local conv (+residual) -> packed V^T [b,h][e][s]; both branches.
// ---------------------------------------------------------------------------
__global__ __launch_bounds__(128) void vconv_fused(
    const float* __restrict__ kv1, const float* __restrict__ lcw1,
    const float* __restrict__ lcb1, uint32_t* __restrict__ v1p,
    const float* __restrict__ kv2, const float* __restrict__ lcw2,
    const float* __restrict__ lcb2, uint32_t* __restrict__ v2p)
{
    int token, HS;
    const float *kv, *lcw, *lcb;
    uint32_t* vtp;
    if (blockIdx.x < BATCH * 256) {
        token = blockIdx.x; HS = 16; kv = kv1; lcw = lcw1; lcb = lcb1; vtp = v1p;
    } else {
        token = blockIdx.x - BATCH * 256; HS = 8; kv = kv2; lcw = lcw2; lcb = lcb2; vtp = v2p;
    }
    const int NS = HS * HS;
    const int b  = token / NS;
    const int s  = token - b * NS;
    const int hs = s / HS, ws = s - hs * HS;
    const int c  = threadIdx.x;

    float acc = lcb[c];
#pragma unroll
    for (int kh = 0; kh < 3; kh++)
#pragma unroll
        for (int kw = 0; kw < 3; kw++) {
            const int ih = hs - 1 + kh, iw = ws - 1 + kw;
            if (ih >= 0 && ih < HS && iw >= 0 && iw < HS)
                acc += kv[((size_t)b * NS + ih * HS + iw) * 256 + 128 + c]
                     * lcw[c * 9 + kh * 3 + kw];
        }
    const float v = kv[(size_t)token * 256 + 128 + c] + acc;
    const int h = c >> 5, e = c & 31;
    vtp[(((size_t)b * 4 + h) * 32 + e) * NS + s] = pack_hilo(v);
}

// ---------------------------------------------------------------------------
// Attention via mma (verified); epilogue writes packed cat.
// ---------------------------------------------------------------------------
template<int NS>
__global__ __launch_bounds__(256) void attn_mma(
    const uint32_t* __restrict__ qp,
    const uint32_t* __restrict__ kp,
    const uint32_t* __restrict__ vtp,
    uint32_t* __restrict__ catp,
    int qoff, int ooff)
{
    constexpr int NSP = NS + 2;
    constexpr int LDQ = 34;
    constexpr int NT  = NS / 32;
    constexpr int LOG = (NS == 256) ? 8 : 6;
    const float scale = 0.17677669529663689f;

    extern __shared__ float smf[];
    uint32_t* Qs = (uint32_t*)smf;
    uint32_t* Ks = Qs + 64 * LDQ;
    float*    Ss = (float*)(Ks + NS * LDQ);
    float*    rs = Ss + 64 * NSP;
    uint32_t* Vs = Ks;
    uint32_t* Sp = (uint32_t*)Ss;

    const int b = blockIdx.x >> 2, h = blockIdx.x & 3;
    const int q0 = blockIdx.y * 64;
    const int tid = threadIdx.x, lane = tid & 31, w = tid >> 5;
    const int g = lane >> 2, qk = (lane & 3) * 2;

    for (int i = tid; i < 64 * 32; i += 256) {
        const int r = i >> 5, e = i & 31;
        Qs[r * LDQ + e] = qp[((size_t)(b * 4096 + q0 + r)) * 256 + qoff + h * 32 + e];
    }
    for (int i = tid; i < NS * 32; i += 256) {
        const int s = i >> 5, e = i & 31;
        Ks[s * LDQ + e] = kp[((size_t)(b * NS + s)) * 128 + h * 32 + e];
    }
    __syncthreads();

    // phase 1: S = Q K^T
    {
        const int wm = w & 1, wn = w >> 1;
        float acc[2][NT][4];
#pragma unroll
        for (int mt = 0; mt < 2; mt++)
#pragma unroll
            for (int nt = 0; nt < NT; nt++)
#pragma unroll
                for (int r = 0; r < 4; r++) acc[mt][nt][r] = 0.f;

#pragma unroll
        for (int kc = 0; kc < 2; kc++) {
            const int kb = kc * 16;
            uint32_t ah[2][4], al[2][4];
#pragma unroll
            for (int mt = 0; mt < 2; mt++) {
                const int row = wm * 32 + mt * 16 + g;
                uint2 p0 = *(const uint2*)&Qs[row * LDQ + kb + qk];
                uint2 p1 = *(const uint2*)&Qs[(row + 8) * LDQ + kb + qk];
                uint2 p2 = *(const uint2*)&Qs[row * LDQ + kb + qk + 8];
                uint2 p3 = *(const uint2*)&Qs[(row + 8) * LDQ + kb + qk + 8];
                ah[mt][0] = __byte_perm(p0.x, p0.y, 0x5410);
                al[mt][0] = __byte_perm(p0.x, p0.y, 0x7632);
                ah[mt][1] = __byte_perm(p1.x, p1.y, 0x5410);
                al[mt][1] = __byte_perm(p1.x, p1.y, 0x7632);
                ah[mt][2] = __byte_perm(p2.x, p2.y, 0x5410);
                al[mt][2] = __byte_perm(p2.x, p2.y, 0x7632);
                ah[mt][3] = __byte_perm(p3.x, p3.y, 0x5410);
                al[mt][3] = __byte_perm(p3.x, p3.y, 0x7632);
            }
            uint32_t bh[NT][2], bl[NT][2];
#pragma unroll
            for (int nt = 0; nt < NT; nt++) {
                const int srow = wn * (NS / 4) + nt * 8 + g;
                uint2 p0 = *(const uint2*)&Ks[srow * LDQ + kb + qk];
                uint2 p1 = *(const uint2*)&Ks[srow * LDQ + kb + qk + 8];
                bh[nt][0] = __byte_perm(p0.x, p0.y, 0x5410);
                bl[nt][0] = __byte_perm(p0.x, p0.y, 0x7632);
                bh[nt][1] = __byte_perm(p1.x, p1.y, 0x5410);
                bl[nt][1] = __byte_perm(p1.x, p1.y, 0x7632);
            }
#pragma unroll
            for (int mt = 0; mt < 2; mt++)
#pragma unroll
                for (int nt = 0; nt < NT; nt++) {
                    mma16816(acc[mt][nt], ah[mt], bh[nt]);
                    mma16816(acc[mt][nt], al[mt], bh[nt]);
                    mma16816(acc[mt][nt], ah[mt], bl[nt]);
                }
        }
#pragma unroll
        for (int mt = 0; mt < 2; mt++) {
            const int r = wm * 32 + mt * 16 + g;
#pragma unroll
            for (int nt = 0; nt < NT; nt++) {
                const int col = wn * (NS / 4) + nt * 8 + qk;
                *(float2*)&Ss[r * NSP + col] =
                    make_float2(acc[mt][nt][0] * scale, acc[mt][nt][1] * scale);
                *(float2*)&Ss[(r + 8) * NSP + col] =
                    make_float2(acc[mt][nt][2] * scale, acc[mt][nt][3] * scale);
            }
        }
    }
    __syncthreads();

    // stage V^T (overwrites Ks)
    for (int i = tid; i < 32 * NS; i += 256) {
        const int e = i >> LOG, s = i & (NS - 1);
        Vs[e * NSP + s] = vtp[(((size_t)(b * 4 + h)) * 32 + e) * NS + s];
    }

    // softmax + pack in place
    {
        constexpr int JN = NS / 32;
#pragma unroll
        for (int i = 0; i < 8; i++) {
            const int r = w * 8 + i;
            float v[JN];
            float mx = -1e30f;
#pragma unroll
            for (int j = 0; j < JN; j++) {
                v[j] = Ss[r * NSP + lane + j * 32];
                mx = fmaxf(mx, v[j]);
            }
#pragma unroll
            for (int o = 16; o > 0; o >>= 1)
                mx = fmaxf(mx, __shfl_xor_sync(0xffffffffu, mx, o));
            float sum = 0.f;
#pragma unroll
            for (int j = 0; j < JN; j++) { v[j] = __expf(v[j] - mx); sum += v[j]; }
#pragma unroll
            for (int o = 16; o > 0; o >>= 1)
                sum += __shfl_xor_sync(0xffffffffu, sum, o);
#pragma unroll
            for (int j = 0; j < JN; j++)
                Sp[r * NSP + lane + j * 32] = pack_hilo(v[j]);
            if (lane == 0) rs[r] = sum;
        }
    }
    __syncthreads();

    // phase 3: O = P V
    {
        const int wm = w & 3, wn = w >> 2;
        float acc[2][4];
#pragma unroll
        for (int nt = 0; nt < 2; nt++)
#pragma unroll
            for (int r = 0; r < 4; r++) acc[nt][r] = 0.f;

#pragma unroll 4
        for (int kc = 0; kc < NS / 16; kc++) {
            const int kb = kc * 16;
            const int row = wm * 16 + g;
            uint32_t ah[4], al[4];
            {
                uint2 p0 = *(const uint2*)&Sp[row * NSP + kb + qk];
                uint2 p1 = *(const uint2*)&Sp[(row + 8) * NSP + kb + qk];
                uint2 p2 = *(const uint2*)&Sp[row * NSP + kb + qk + 8];
                uint2 p3 = *(const uint2*)&Sp[(row + 8) * NSP + kb + qk + 8];
                ah[0] = __byte_perm(p0.x, p0.y, 0x5410);
                al[0] = __byte_perm(p0.x, p0.y, 0x7632);
                ah[1] = __byte_perm(p1.x, p1.y, 0x5410);
                al[1] = __byte_perm(p1.x, p1.y, 0x7632);
                ah[2] = __byte_perm(p2.x, p2.y, 0x5410);
                al[2] = __byte_perm(p2.x, p2.y, 0x7632);
                ah[3] = __byte_perm(p3.x, p3.y, 0x5410);
                al[3] = __byte_perm(p3.x, p3.y, 0x7632);
            }
            uint32_t bh[2][2], bl[2][2];
#pragma unroll
            for (int nt = 0; nt < 2; nt++) {
                const int e = wn * 16 + nt * 8 + g;
                uint2 p0 = *(const uint2*)&Vs[e * NSP + kb + qk];
                uint2 p1 = *(const uint2*)&Vs[e * NSP + kb + qk + 8];
                bh[nt][0] = __byte_perm(p0.x, p0.y, 0x5410);
                bl[nt][0] = __byte_perm(p0.x, p0.y, 0x7632);
                bh[nt][1] = __byte_perm(p1.x, p1.y, 0x5410);
                bl[nt][1] = __byte_perm(p1.x, p1.y, 0x7632);
            }
#pragma unroll
            for (int nt = 0; nt < 2; nt++) {
                mma16816(acc[nt], ah, bh[nt]);
                mma16816(acc[nt], al, bh[nt]);
                mma16816(acc[nt], ah, bl[nt]);
            }
        }

        const int r0 = wm * 16 + g;
        const float inv0 = 1.0f / rs[r0];
        const float inv1 = 1.0f / rs[r0 + 8];
#pragma unroll
        for (int nt = 0; nt < 2; nt++) {
            const int col = ooff + h * 32 + wn * 16 + nt * 8 + qk;
            *(uint2*)&catp[((size_t)(b * 4096 + q0 + r0)) * 256 + col] =
                make_uint2(pack_hilo(acc[nt][0] * inv0), pack_hilo(acc[nt][1] * inv0));
            *(uint2*)&catp[((size_t)(b * 4096 + q0 + r0 + 8)) * 256 + col] =
                make_uint2(pack_hilo(acc[nt][2] * inv1), pack_hilo(acc[nt][3] * inv1));
        }
    }
}

// ---------------------------------------------------------------------------
// launch
// ---------------------------------------------------------------------------
extern "C" void kernel_launch(void* const* d_in, const int* in_sizes, int n_in,
                              void* d_out, int out_size)
{
    const float* x      = (const float*)d_in[0];
    const float* q_w    = (const float*)d_in[1];
    const float* kv1_w  = (const float*)d_in[2];
    const float* kv2_w  = (const float*)d_in[3];
    const float* proj_w = (const float*)d_in[4];
    const float* proj_b = (const float*)d_in[5];
    const float* sr1_w  = (const float*)d_in[6];
    const float* sr1_b  = (const float*)d_in[7];
    const float* sr2_w  = (const float*)d_in[8];
    const float* sr2_b  = (const float*)d_in[9];
    const float* ln1_g  = (const float*)d_in[10];
    const float* ln1_b  = (const float*)d_in[11];
    const float* ln2_g  = (const float*)d_in[12];
    const float* ln2_b  = (const float*)d_in[13];
    const float* lc1_w  = (const float*)d_in[14];
    const float* lc1_b  = (const float*)d_in[15];
    const float* lc2_w  = (const float*)d_in[16];
    const float* lc2_b  = (const float*)d_in[17];
    float* out = (float*)d_out;

    uint32_t *p_xp, *p_qp, *p_catp, *p_x1p, *p_x2p, *p_k1p, *p_k2p, *p_v1p, *p_v2p;
    float *p_kv1, *p_kv2;
    __nv_bfloat16 *p_qwh, *p_qwl, *p_k1wh, *p_k1wl, *p_k2wh, *p_k2wl, *p_pwh, *p_pwl;
    cudaGetSymbolAddress((void**)&p_xp,   g_xp);
    cudaGetSymbolAddress((void**)&p_qp,   g_qp);
    cudaGetSymbolAddress((void**)&p_catp, g_catp);
    cudaGetSymbolAddress((void**)&p_x1p,  g_x1p);
    cudaGetSymbolAddress((void**)&p_x2p,  g_x2p);
    cudaGetSymbolAddress((void**)&p_kv1,  g_kv1);
    cudaGetSymbolAddress((void**)&p_kv2,  g_kv2);
    cudaGetSymbolAddress((void**)&p_k1p,  g_k1p);
    cudaGetSymbolAddress((void**)&p_k2p,  g_k2p);
    cudaGetSymbolAddress((void**)&p_v1p,  g_v1p);
    cudaGetSymbolAddress((void**)&p_v2p,  g_v2p);
    cudaGetSymbolAddress((void**)&p_qwh,  g_qwh);
    cudaGetSymbolAddress((void**)&p_qwl,  g_qwl);
    cudaGetSymbolAddress((void**)&p_k1wh, g_k1wh);
    cudaGetSymbolAddress((void**)&p_k1wl, g_k1wl);
    cudaGetSymbolAddress((void**)&p_k2wh, g_k2wh);
    cudaGetSymbolAddress((void**)&p_k2wl, g_k2wl);
    cudaGetSymbolAddress((void**)&p_pwh,  g_pwh);
    cudaGetSymbolAddress((void**)&p_pwl,  g_pwl);

    const int smem_gemm = 3 * (128 * 40 * 4) + 2 * (3 * 256 * 40 * 2);  // 184,320
    const int smem_dw   = 80 * 257 * 4 + 128;
    const int smem_a1   = (64 * 34 + 256 * 34) * 4 + 64 * 258 * 4 + 64 * 4;
    const int smem_a2   = (64 * 34 + 64 * 34) * 4 + 64 * 66 * 4 + 64 * 4;
    cudaFuncSetAttribute(gemm_pk<0>, cudaFuncAttributeMaxDynamicSharedMemorySize, smem_gemm);
    cudaFuncSetAttribute(gemm_pk<1>, cudaFuncAttributeMaxDynamicSharedMemorySize, smem_gemm);
    cudaFuncSetAttribute(gemm_kv,    cudaFuncAttributeMaxDynamicSharedMemorySize, smem_gemm);
    cudaFuncSetAttribute(dwconv_fused, cudaFuncAttributeMaxDynamicSharedMemorySize, smem_dw);
    cudaFuncSetAttribute(attn_mma<256>, cudaFuncAttributeMaxDynamicSharedMemorySize, smem_a1);
    cudaFuncSetAttribute(attn_mma<64>,  cudaFuncAttributeMaxDynamicSharedMemorySize, smem_a2);

    // 0: all input splits (weights + x)
    split_all<<<9216, 256>>>(x, p_xp, q_w, kv1_w, kv2_w, proj_w,
                             p_qwh, p_qwl, p_k1wh, p_k1wl,
                             p_k2wh, p_k2wl, p_pwh, p_pwl);
    // 1: fused spatial-reduction convs -> packed x1/x2
    dwconv_fused<<<256, 512, smem_dw>>>(
        x, sr1_w, sr1_b, ln1_g, ln1_b, sr2_w, sr2_b, ln2_g, ln2_b, p_x1p, p_x2p);
    // 2: combined kv projections -> fp32 kv + packed k
    gemm_kv<<<20, 512, smem_gemm>>>(p_x1p, p_x2p, p_k1wh, p_k1wl,
                                    p_k2wh, p_k2wl, p_kv1, p_kv2, p_k1p, p_k2p);
    // 3: q projection (PROFILED SLOT)
    gemm_pk<1><<<256, 512, smem_gemm>>>(p_xp, p_qwh, p_qwl, nullptr, nullptr, p_qp);
    // 4: fused v local conv -> packed V^T
    vconv_fused<<<BATCH * 256 + BATCH * 64, 128>>>(
        p_kv1, lc1_w, lc1_b, p_v1p, p_kv2, lc2_w, lc2_b, p_v2p);
    // 5/6: attention -> packed cat
    attn_mma<256><<<dim3(32, 64), 256, smem_a1>>>(p_qp, p_k1p, p_v1p, p_catp, 0,   0);
    attn_mma<64 ><<<dim3(32, 64), 256, smem_a2>>>(p_qp, p_k2p, p_v2p, p_catp, 128, 128);
    // 7: output projection
    gemm_pk<0><<<256, 512, smem_gemm>>>(p_catp, p_pwh, p_pwl, proj_b, out, nullptr);
}